// round 1
// baseline (speedup 1.0000x reference)
#include <cuda_runtime.h>
#include <math.h>

// Problem constants (fixed by reference setup_inputs)
#define NTOK 6144          // B*L = 64*96
#define DMODEL 256
#define NHEAD 8
#define DKH 32
#define NLAYER 2
#define NVOCAB 1024
#define LSEQ 96
#define NBATCH 64

// ---------------------------------------------------------------------------
// Scratch (static device globals; no runtime allocation allowed)
// ---------------------------------------------------------------------------
__device__ float g_x  [NTOK * DMODEL];        // residual stream
__device__ float g_xn [NTOK * DMODEL];        // layernorm output
__device__ float g_qkv[NTOK * 3 * DMODEL];    // qkv projection
__device__ float g_att[NTOK * DMODEL];        // attention output (wv/z)
__device__ float g_mid[NTOK * 4 * DMODEL];    // FFN hidden

// ---------------------------------------------------------------------------
// Embedding: x = coord_emb[pos%3] + pos_emb[pos/3] + value_emb[tok]
// ---------------------------------------------------------------------------
__global__ void embed_k(const int* __restrict__ tok, const int* __restrict__ pos,
                        const float* __restrict__ ve, const float* __restrict__ ce,
                        const float* __restrict__ pe, float* __restrict__ x)
{
    int n = blockIdx.x;
    int d = threadIdx.x;
    int p = pos[n];
    x[n * DMODEL + d] = ce[(p % 3) * DMODEL + d]
                      + pe[(p / 3) * DMODEL + d]
                      + ve[tok[n] * DMODEL + d];
}

// ---------------------------------------------------------------------------
// LayerNorm: one block per row, 256 threads (== DMODEL)
// ---------------------------------------------------------------------------
__global__ void ln_k(const float* __restrict__ x, const float* __restrict__ s,
                     const float* __restrict__ b, float* __restrict__ y)
{
    __shared__ float red[DMODEL];
    int n = blockIdx.x, t = threadIdx.x;
    float v = x[n * DMODEL + t];

    red[t] = v;
    __syncthreads();
    #pragma unroll
    for (int o = DMODEL / 2; o > 0; o >>= 1) {
        if (t < o) red[t] += red[t + o];
        __syncthreads();
    }
    float mu = red[0] * (1.0f / DMODEL);
    __syncthreads();

    float dlt = v - mu;
    red[t] = dlt * dlt;
    __syncthreads();
    #pragma unroll
    for (int o = DMODEL / 2; o > 0; o >>= 1) {
        if (t < o) red[t] += red[t + o];
        __syncthreads();
    }
    float var = red[0] * (1.0f / DMODEL);

    y[n * DMODEL + t] = dlt * rsqrtf(var + 1e-5f) * s[t] + b[t];
}

// ---------------------------------------------------------------------------
// Dense causal attention, one block per (batch, head). 128 threads; threads
// 0..95 each own one destination position. K/V staged in smem (warp reads of
// ks[s][d] are uniform across the warp -> broadcast, conflict-free).
// ---------------------------------------------------------------------------
__global__ void attn_k(const float* __restrict__ qkv, float* __restrict__ o)
{
    __shared__ float ks[LSEQ][DKH];
    __shared__ float vs[LSEQ][DKH];
    int bh = blockIdx.x;
    int b  = bh / NHEAD;
    int h  = bh % NHEAD;
    int base = b * LSEQ;
    int tid = threadIdx.x;

    for (int i = tid; i < LSEQ * DKH; i += 128) {
        int r = i / DKH, d = i % DKH;
        const float* row = qkv + (size_t)(base + r) * (3 * DMODEL) + h * DKH + d;
        ks[r][d] = row[DMODEL];
        vs[r][d] = row[2 * DMODEL];
    }
    __syncthreads();

    int t = tid;
    if (t < LSEQ) {
        float q[DKH];
        const float* qrow = qkv + (size_t)(base + t) * (3 * DMODEL) + h * DKH;
        #pragma unroll
        for (int d = 0; d < DKH; d++) q[d] = qrow[d];

        float wv[DKH];
        #pragma unroll
        for (int d = 0; d < DKH; d++) wv[d] = 0.0f;
        float z = 0.0f;
        const float invs = 0.17677669529663687f;   // 1/sqrt(32)

        for (int s = 0; s <= t; s++) {
            float dot = 0.0f;
            #pragma unroll
            for (int d = 0; d < DKH; d++) dot += q[d] * ks[s][d];
            float a = fminf(fmaxf(dot * invs, -5.0f), 5.0f);
            float w = expf(a);
            z += w;
            #pragma unroll
            for (int d = 0; d < DKH; d++) wv[d] += w * vs[s][d];
        }
        float inv = 1.0f / z;
        float* orow = o + (size_t)(base + t) * DMODEL + h * DKH;
        #pragma unroll
        for (int d = 0; d < DKH; d++) orow[d] = wv[d] * inv;
    }
}

// ---------------------------------------------------------------------------
// SGEMM: C[M,N] = A[M,K] @ B[K,N] + bias[N]  (+ epilogue)
//   OP 0: bias only     OP 1: bias + relu     OP 2: bias + residual add
// 128x128 block tile, 8x8 per-thread microtile, BK=8, 256 threads.
// All M,N multiples of 128 and K multiples of 8 in this problem -> no guards.
// ---------------------------------------------------------------------------
template<int OP>
__global__ __launch_bounds__(256, 2)
void sgemm_k(const float* __restrict__ A, const float* __restrict__ B,
             const float* __restrict__ bias, const float* __restrict__ res,
             float* __restrict__ C, int M, int Nn, int K)
{
    __shared__ float As[8][132];   // padded: conflict-free transposed stores
    __shared__ float Bs[8][128];

    int tid = threadIdx.x;
    int m0 = blockIdx.y * 128;
    int n0 = blockIdx.x * 128;
    int tx = tid & 15;       // col group
    int ty = tid >> 4;       // row group

    float acc[8][8];
    #pragma unroll
    for (int i = 0; i < 8; i++)
        #pragma unroll
        for (int j = 0; j < 8; j++) acc[i][j] = 0.0f;

    int arow = tid >> 1;             // 0..127
    int akq  = (tid & 1) * 4;        // 0 or 4
    int bk   = tid >> 5;             // 0..7
    int bc   = (tid & 31) * 4;       // 0..124

    const float* Aptr = A + (size_t)(m0 + arow) * K + akq;
    const float* Bptr = B + (size_t)bk * Nn + n0 + bc;

    for (int kt = 0; kt < K; kt += 8) {
        float4 av = *(const float4*)(Aptr + kt);
        float4 bv = *(const float4*)(Bptr + (size_t)kt * Nn);
        As[akq + 0][arow] = av.x;
        As[akq + 1][arow] = av.y;
        As[akq + 2][arow] = av.z;
        As[akq + 3][arow] = av.w;
        *(float4*)&Bs[bk][bc] = bv;
        __syncthreads();

        #pragma unroll
        for (int k = 0; k < 8; k++) {
            float a[8], bb[8];
            float4 a0 = *(const float4*)&As[k][ty * 8];
            float4 a1 = *(const float4*)&As[k][ty * 8 + 4];
            a[0]=a0.x; a[1]=a0.y; a[2]=a0.z; a[3]=a0.w;
            a[4]=a1.x; a[5]=a1.y; a[6]=a1.z; a[7]=a1.w;
            float4 b0 = *(const float4*)&Bs[k][tx * 8];
            float4 b1 = *(const float4*)&Bs[k][tx * 8 + 4];
            bb[0]=b0.x; bb[1]=b0.y; bb[2]=b0.z; bb[3]=b0.w;
            bb[4]=b1.x; bb[5]=b1.y; bb[6]=b1.z; bb[7]=b1.w;
            #pragma unroll
            for (int i = 0; i < 8; i++)
                #pragma unroll
                for (int j = 0; j < 8; j++)
                    acc[i][j] += a[i] * bb[j];
        }
        __syncthreads();
    }

    // epilogue
    #pragma unroll
    for (int i = 0; i < 8; i++) {
        int row = m0 + ty * 8 + i;
        #pragma unroll
        for (int j4 = 0; j4 < 2; j4++) {
            int col = n0 + tx * 8 + j4 * 4;
            float4 v;
            v.x = acc[i][j4 * 4 + 0] + bias[col + 0];
            v.y = acc[i][j4 * 4 + 1] + bias[col + 1];
            v.z = acc[i][j4 * 4 + 2] + bias[col + 2];
            v.w = acc[i][j4 * 4 + 3] + bias[col + 3];
            if (OP == 1) {
                v.x = fmaxf(v.x, 0.0f); v.y = fmaxf(v.y, 0.0f);
                v.z = fmaxf(v.z, 0.0f); v.w = fmaxf(v.w, 0.0f);
            }
            if (OP == 2) {
                float4 r = *(const float4*)(res + (size_t)row * Nn + col);
                v.x += r.x; v.y += r.y; v.z += r.z; v.w += r.w;
            }
            *(float4*)(C + (size_t)row * Nn + col) = v;
        }
    }
}

// ---------------------------------------------------------------------------
// In-place log_softmax over VOCAB=1024, one block per row, 256 threads x 4.
// ---------------------------------------------------------------------------
__global__ void lsm_k(float* __restrict__ out)
{
    __shared__ float red[256];
    int n = blockIdx.x, t = threadIdx.x;
    float v[4];
    #pragma unroll
    for (int j = 0; j < 4; j++) v[j] = out[(size_t)n * NVOCAB + t + j * 256];

    float m = fmaxf(fmaxf(v[0], v[1]), fmaxf(v[2], v[3]));
    red[t] = m;
    __syncthreads();
    #pragma unroll
    for (int o = 128; o > 0; o >>= 1) {
        if (t < o) red[t] = fmaxf(red[t], red[t + o]);
        __syncthreads();
    }
    float M = red[0];
    __syncthreads();

    float s = 0.0f;
    #pragma unroll
    for (int j = 0; j < 4; j++) s += expf(v[j] - M);
    red[t] = s;
    __syncthreads();
    #pragma unroll
    for (int o = 128; o > 0; o >>= 1) {
        if (t < o) red[t] += red[t + o];
        __syncthreads();
    }
    float lse = M + logf(red[0]);

    #pragma unroll
    for (int j = 0; j < 4; j++)
        out[(size_t)n * NVOCAB + t + j * 256] = v[j] - lse;
}

// ---------------------------------------------------------------------------
// Launch
// ---------------------------------------------------------------------------
extern "C" void kernel_launch(void* const* d_in, const int* in_sizes, int n_in,
                              void* d_out, int out_size)
{
    const int*   tokens    = (const int*)  d_in[0];
    const int*   pos_idx   = (const int*)  d_in[1];
    // d_in[2], d_in[3]: edge_src/edge_dst — structurally causal, handled densely
    const float* value_emb = (const float*)d_in[4];
    const float* coord_emb = (const float*)d_in[5];
    const float* pos_emb   = (const float*)d_in[6];
    const float* ln1_s     = (const float*)d_in[7];
    const float* ln1_b     = (const float*)d_in[8];
    const float* W_qkv     = (const float*)d_in[9];
    const float* b_qkv     = (const float*)d_in[10];
    const float* W_o       = (const float*)d_in[11];
    const float* b_o       = (const float*)d_in[12];
    const float* ln2_s     = (const float*)d_in[13];
    const float* ln2_b     = (const float*)d_in[14];
    const float* W_ff1     = (const float*)d_in[15];
    const float* b_ff1     = (const float*)d_in[16];
    const float* W_ff2     = (const float*)d_in[17];
    const float* b_ff2     = (const float*)d_in[18];
    const float* W_gen     = (const float*)d_in[19];
    const float* b_gen     = (const float*)d_in[20];
    float* out = (float*)d_out;

    float *x, *xn, *qkv, *att, *mid;
    cudaGetSymbolAddress((void**)&x,   g_x);
    cudaGetSymbolAddress((void**)&xn,  g_xn);
    cudaGetSymbolAddress((void**)&qkv, g_qkv);
    cudaGetSymbolAddress((void**)&att, g_att);
    cudaGetSymbolAddress((void**)&mid, g_mid);

    embed_k<<<NTOK, DMODEL>>>(tokens, pos_idx, value_emb, coord_emb, pos_emb, x);

    for (int l = 0; l < NLAYER; l++) {
        const float* wqkv = W_qkv + (size_t)l * DMODEL * 3 * DMODEL;
        const float* bqkv = b_qkv + (size_t)l * 3 * DMODEL;
        const float* wo   = W_o   + (size_t)l * DMODEL * DMODEL;
        const float* bo   = b_o   + (size_t)l * DMODEL;
        const float* wf1  = W_ff1 + (size_t)l * DMODEL * 4 * DMODEL;
        const float* bf1  = b_ff1 + (size_t)l * 4 * DMODEL;
        const float* wf2  = W_ff2 + (size_t)l * 4 * DMODEL * DMODEL;
        const float* bf2  = b_ff2 + (size_t)l * DMODEL;

        ln_k<<<NTOK, DMODEL>>>(x, ln1_s + l * DMODEL, ln1_b + l * DMODEL, xn);

        { dim3 g(3 * DMODEL / 128, NTOK / 128);
          sgemm_k<0><<<g, 256>>>(xn, wqkv, bqkv, nullptr, qkv, NTOK, 3 * DMODEL, DMODEL); }

        attn_k<<<NBATCH * NHEAD, 128>>>(qkv, att);

        { dim3 g(DMODEL / 128, NTOK / 128);
          sgemm_k<2><<<g, 256>>>(att, wo, bo, x, x, NTOK, DMODEL, DMODEL); }

        ln_k<<<NTOK, DMODEL>>>(x, ln2_s + l * DMODEL, ln2_b + l * DMODEL, xn);

        { dim3 g(4 * DMODEL / 128, NTOK / 128);
          sgemm_k<1><<<g, 256>>>(xn, wf1, bf1, nullptr, mid, NTOK, 4 * DMODEL, DMODEL); }

        { dim3 g(DMODEL / 128, NTOK / 128);
          sgemm_k<2><<<g, 256>>>(mid, wf2, bf2, x, x, NTOK, DMODEL, 4 * DMODEL); }
    }

    { dim3 g(NVOCAB / 128, NTOK / 128);
      sgemm_k<0><<<g, 256>>>(x, W_gen, b_gen, nullptr, out, NTOK, NVOCAB, DMODEL); }

    lsm_k<<<NTOK, 256>>>(out);
}

// round 2
// speedup vs baseline: 2.5173x; 2.5173x over previous
#include <cuda_runtime.h>
#include <math.h>

#define NTOK 6144
#define DMODEL 256
#define NHEAD 8
#define DKH 32
#define NLAYER 2
#define NVOCAB 1024
#define LSEQ 96
#define NBATCH 64

// ---------------------------------------------------------------------------
// Scratch
// ---------------------------------------------------------------------------
__device__ float g_x  [NTOK * DMODEL];
__device__ float g_xn [NTOK * DMODEL];
__device__ float g_qkv[NTOK * 3 * DMODEL];
__device__ float g_att[NTOK * DMODEL];
__device__ float g_mid[NTOK * 4 * DMODEL];

// ---------------------------------------------------------------------------
// Embedding
// ---------------------------------------------------------------------------
__global__ void embed_k(const int* __restrict__ tok, const int* __restrict__ pos,
                        const float* __restrict__ ve, const float* __restrict__ ce,
                        const float* __restrict__ pe, float* __restrict__ x)
{
    int n = blockIdx.x;
    int d = threadIdx.x;
    int p = pos[n];
    x[n * DMODEL + d] = ce[(p % 3) * DMODEL + d]
                      + pe[(p / 3) * DMODEL + d]
                      + ve[tok[n] * DMODEL + d];
}

// ---------------------------------------------------------------------------
// LayerNorm: one warp per row, float4 I/O, shfl reductions.
// ---------------------------------------------------------------------------
__global__ void ln_k(const float* __restrict__ x, const float* __restrict__ s,
                     const float* __restrict__ b, float* __restrict__ y)
{
    int row  = blockIdx.x * 8 + (threadIdx.x >> 5);
    int lane = threadIdx.x & 31;
    const float4* xr = (const float4*)(x + (size_t)row * DMODEL);
    float4 v0 = xr[lane];
    float4 v1 = xr[lane + 32];

    float sum = v0.x + v0.y + v0.z + v0.w + v1.x + v1.y + v1.z + v1.w;
    #pragma unroll
    for (int o = 16; o > 0; o >>= 1) sum += __shfl_xor_sync(0xffffffffu, sum, o);
    float mu = sum * (1.0f / DMODEL);

    float d0x=v0.x-mu, d0y=v0.y-mu, d0z=v0.z-mu, d0w=v0.w-mu;
    float d1x=v1.x-mu, d1y=v1.y-mu, d1z=v1.z-mu, d1w=v1.w-mu;
    float sq = d0x*d0x+d0y*d0y+d0z*d0z+d0w*d0w + d1x*d1x+d1y*d1y+d1z*d1z+d1w*d1w;
    #pragma unroll
    for (int o = 16; o > 0; o >>= 1) sq += __shfl_xor_sync(0xffffffffu, sq, o);
    float rs = rsqrtf(sq * (1.0f / DMODEL) + 1e-5f);

    const float4* sv = (const float4*)s;
    const float4* bv = (const float4*)b;
    float4* yr = (float4*)(y + (size_t)row * DMODEL);
    float4 s0 = sv[lane], s1 = sv[lane + 32];
    float4 b0 = bv[lane], b1 = bv[lane + 32];
    float4 o0, o1;
    o0.x = d0x*rs*s0.x + b0.x;  o0.y = d0y*rs*s0.y + b0.y;
    o0.z = d0z*rs*s0.z + b0.z;  o0.w = d0w*rs*s0.w + b0.w;
    o1.x = d1x*rs*s1.x + b1.x;  o1.y = d1y*rs*s1.y + b1.y;
    o1.z = d1z*rs*s1.z + b1.z;  o1.w = d1w*rs*s1.w + b1.w;
    yr[lane] = o0;
    yr[lane + 32] = o1;
}

// ---------------------------------------------------------------------------
// Attention: one block per (batch, head), 384 threads.
// Each dst position t owned by 4 threads (j = tid&3) splitting the s-loop;
// partials combined via shfl_xor. K/V staged in padded smem (conflict-free).
// ---------------------------------------------------------------------------
__global__ void attn_k(const float* __restrict__ qkv, float* __restrict__ o)
{
    __shared__ float ks[LSEQ][DKH + 1];
    __shared__ float vs[LSEQ][DKH + 1];
    int bh = blockIdx.x;
    int b  = bh >> 3;
    int h  = bh & 7;
    int base = b * LSEQ;
    int tid = threadIdx.x;

    for (int i = tid; i < LSEQ * DKH; i += 384) {
        int r = i >> 5, d = i & 31;
        const float* row = qkv + (size_t)(base + r) * (3 * DMODEL) + h * DKH + d;
        ks[r][d] = row[DMODEL];
        vs[r][d] = row[2 * DMODEL];
    }
    __syncthreads();

    int t = tid >> 2;
    int j = tid & 3;

    float q[DKH];
    {
        const float4* qrow = (const float4*)(qkv + (size_t)(base + t) * (3 * DMODEL) + h * DKH);
        #pragma unroll
        for (int i = 0; i < 8; i++) {
            float4 v = qrow[i];
            q[i*4+0]=v.x; q[i*4+1]=v.y; q[i*4+2]=v.z; q[i*4+3]=v.w;
        }
    }

    float wv[DKH];
    #pragma unroll
    for (int d = 0; d < DKH; d++) wv[d] = 0.0f;
    float z = 0.0f;
    const float invs = 0.17677669529663687f;

    for (int s = j; s <= t; s += 4) {
        float dot = 0.0f;
        #pragma unroll
        for (int d = 0; d < DKH; d++) dot += q[d] * ks[s][d];
        float a = fminf(fmaxf(dot * invs, -5.0f), 5.0f);
        float w = __expf(a) ;
        // match expf precision closely: use expf (accurate) to stay safe
        w = expf(a);
        z += w;
        #pragma unroll
        for (int d = 0; d < DKH; d++) wv[d] += w * vs[s][d];
    }

    #pragma unroll
    for (int off = 1; off <= 2; off <<= 1) {
        z += __shfl_xor_sync(0xffffffffu, z, off);
        #pragma unroll
        for (int d = 0; d < DKH; d++)
            wv[d] += __shfl_xor_sync(0xffffffffu, wv[d], off);
    }

    if (j == 0) {
        float inv = 1.0f / z;
        float4* orow = (float4*)(o + (size_t)(base + t) * DMODEL + h * DKH);
        #pragma unroll
        for (int i = 0; i < 8; i++) {
            float4 v;
            v.x = wv[i*4+0]*inv; v.y = wv[i*4+1]*inv;
            v.z = wv[i*4+2]*inv; v.w = wv[i*4+3]*inv;
            orow[i] = v;
        }
    }
}

// ---------------------------------------------------------------------------
// tf32 tensor-core GEMM: C[M,N] = A[M,K] @ B[K,N] + bias (+relu / +residual)
// 128x128 block tile, KT=16, double-buffered smem, 8 warps (32x64 warp tile),
// mma.sync.m16n8k8 tf32. M%128==0, N%128==0, K%16==0 guaranteed.
// ---------------------------------------------------------------------------
__device__ __forceinline__ unsigned f2t(float x)
{
    unsigned u;
    asm("cvt.rna.tf32.f32 %0, %1;" : "=r"(u) : "f"(x));
    return u;
}

__device__ __forceinline__ void mma_tf32(float* c, unsigned a0, unsigned a1,
                                         unsigned a2, unsigned a3,
                                         unsigned b0, unsigned b1)
{
    asm volatile(
        "mma.sync.aligned.m16n8k8.row.col.f32.tf32.tf32.f32 "
        "{%0,%1,%2,%3}, {%4,%5,%6,%7}, {%8,%9}, {%0,%1,%2,%3};"
        : "+f"(c[0]), "+f"(c[1]), "+f"(c[2]), "+f"(c[3])
        : "r"(a0), "r"(a1), "r"(a2), "r"(a3), "r"(b0), "r"(b1));
}

template<int OP>   // 0: bias, 1: bias+relu, 2: bias+residual
__global__ __launch_bounds__(256, 2)
void tgemm_k(const float* __restrict__ A, const float* __restrict__ B,
             const float* __restrict__ bias, const float* __restrict__ res,
             float* __restrict__ C, int M, int N, int K)
{
    __shared__ unsigned As[2][128][20];   // [m][k] row-major, stride 20 (conflict-free frags)
    __shared__ unsigned Bs[2][16][136];   // [k][n], stride 136 (conflict-free frags)

    int tid  = threadIdx.x;
    int lane = tid & 31;
    int wid  = tid >> 5;
    int g  = lane >> 2;
    int lt = lane & 3;
    int wm = (wid & 3) * 32;
    int wn = (wid >> 2) * 64;
    int m0 = blockIdx.y * 128;
    int n0 = blockIdx.x * 128;

    int ar = tid >> 2;          // 0..63
    int ac = (tid & 3) * 4;     // 0,4,8,12
    int br = tid >> 5;          // 0..7
    int bc = (tid & 31) * 4;    // 0..124

    const float* Ap  = A + (size_t)(m0 + ar) * K + ac;
    const float* Ap2 = Ap + (size_t)64 * K;
    const float* Bp  = B + (size_t)br * N + n0 + bc;
    const float* Bp2 = Bp + (size_t)8 * N;

    float acc[2][8][4];
    #pragma unroll
    for (int i = 0; i < 2; i++)
        #pragma unroll
        for (int j = 0; j < 8; j++)
            #pragma unroll
            for (int v = 0; v < 4; v++) acc[i][j][v] = 0.0f;

    int T = K >> 4;
    float4 a0v = *(const float4*)(Ap);
    float4 a1v = *(const float4*)(Ap2);
    float4 b0v = *(const float4*)(Bp);
    float4 b1v = *(const float4*)(Bp2);

    for (int kt = 0; kt < T; kt++) {
        int buf = kt & 1;
        {
            uint4 u;
            u.x=f2t(a0v.x); u.y=f2t(a0v.y); u.z=f2t(a0v.z); u.w=f2t(a0v.w);
            *(uint4*)&As[buf][ar][ac] = u;
            u.x=f2t(a1v.x); u.y=f2t(a1v.y); u.z=f2t(a1v.z); u.w=f2t(a1v.w);
            *(uint4*)&As[buf][ar + 64][ac] = u;
            u.x=f2t(b0v.x); u.y=f2t(b0v.y); u.z=f2t(b0v.z); u.w=f2t(b0v.w);
            *(uint4*)&Bs[buf][br][bc] = u;
            u.x=f2t(b1v.x); u.y=f2t(b1v.y); u.z=f2t(b1v.z); u.w=f2t(b1v.w);
            *(uint4*)&Bs[buf][br + 8][bc] = u;
        }
        __syncthreads();

        if (kt + 1 < T) {
            int ko = (kt + 1) * 16;
            a0v = *(const float4*)(Ap + ko);
            a1v = *(const float4*)(Ap2 + ko);
            b0v = *(const float4*)(Bp + (size_t)ko * N);
            b1v = *(const float4*)(Bp2 + (size_t)ko * N);
        }

        #pragma unroll
        for (int kk = 0; kk < 16; kk += 8) {
            unsigned af[2][4], bf[8][2];
            #pragma unroll
            for (int i = 0; i < 2; i++) {
                af[i][0] = As[buf][wm + 16*i + g    ][kk + lt];
                af[i][1] = As[buf][wm + 16*i + g + 8][kk + lt];
                af[i][2] = As[buf][wm + 16*i + g    ][kk + lt + 4];
                af[i][3] = As[buf][wm + 16*i + g + 8][kk + lt + 4];
            }
            #pragma unroll
            for (int j = 0; j < 8; j++) {
                bf[j][0] = Bs[buf][kk + lt    ][wn + 8*j + g];
                bf[j][1] = Bs[buf][kk + lt + 4][wn + 8*j + g];
            }
            #pragma unroll
            for (int i = 0; i < 2; i++)
                #pragma unroll
                for (int j = 0; j < 8; j++)
                    mma_tf32(acc[i][j], af[i][0], af[i][1], af[i][2], af[i][3],
                             bf[j][0], bf[j][1]);
        }
    }

    // epilogue: c0,c1 -> (row r0, col c,c+1); c2,c3 -> (r0+8, c,c+1)
    #pragma unroll
    for (int i = 0; i < 2; i++) {
        int r0 = m0 + wm + 16*i + g;
        #pragma unroll
        for (int j = 0; j < 8; j++) {
            int c = n0 + wn + 8*j + 2*lt;
            float bx = bias[c], by = bias[c + 1];
            float2 v0, v1;
            v0.x = acc[i][j][0] + bx;  v0.y = acc[i][j][1] + by;
            v1.x = acc[i][j][2] + bx;  v1.y = acc[i][j][3] + by;
            if (OP == 1) {
                v0.x = fmaxf(v0.x, 0.0f); v0.y = fmaxf(v0.y, 0.0f);
                v1.x = fmaxf(v1.x, 0.0f); v1.y = fmaxf(v1.y, 0.0f);
            }
            if (OP == 2) {
                float2 r0v = *(const float2*)(res + (size_t)r0 * N + c);
                float2 r1v = *(const float2*)(res + (size_t)(r0 + 8) * N + c);
                v0.x += r0v.x; v0.y += r0v.y;
                v1.x += r1v.x; v1.y += r1v.y;
            }
            *(float2*)(C + (size_t)r0 * N + c) = v0;
            *(float2*)(C + (size_t)(r0 + 8) * N + c) = v1;
        }
    }
}

// ---------------------------------------------------------------------------
// In-place log_softmax over VOCAB=1024
// ---------------------------------------------------------------------------
__global__ void lsm_k(float* __restrict__ out)
{
    __shared__ float red[256];
    int n = blockIdx.x, t = threadIdx.x;
    float v[4];
    #pragma unroll
    for (int j = 0; j < 4; j++) v[j] = out[(size_t)n * NVOCAB + t + j * 256];

    float m = fmaxf(fmaxf(v[0], v[1]), fmaxf(v[2], v[3]));
    red[t] = m;
    __syncthreads();
    #pragma unroll
    for (int o = 128; o > 0; o >>= 1) {
        if (t < o) red[t] = fmaxf(red[t], red[t + o]);
        __syncthreads();
    }
    float M = red[0];
    __syncthreads();

    float s = 0.0f;
    #pragma unroll
    for (int j = 0; j < 4; j++) s += expf(v[j] - M);
    red[t] = s;
    __syncthreads();
    #pragma unroll
    for (int o = 128; o > 0; o >>= 1) {
        if (t < o) red[t] += red[t + o];
        __syncthreads();
    }
    float lse = M + logf(red[0]);

    #pragma unroll
    for (int j = 0; j < 4; j++)
        out[(size_t)n * NVOCAB + t + j * 256] = v[j] - lse;
}

// ---------------------------------------------------------------------------
// Launch
// ---------------------------------------------------------------------------
extern "C" void kernel_launch(void* const* d_in, const int* in_sizes, int n_in,
                              void* d_out, int out_size)
{
    const int*   tokens    = (const int*)  d_in[0];
    const int*   pos_idx   = (const int*)  d_in[1];
    const float* value_emb = (const float*)d_in[4];
    const float* coord_emb = (const float*)d_in[5];
    const float* pos_emb   = (const float*)d_in[6];
    const float* ln1_s     = (const float*)d_in[7];
    const float* ln1_b     = (const float*)d_in[8];
    const float* W_qkv     = (const float*)d_in[9];
    const float* b_qkv     = (const float*)d_in[10];
    const float* W_o       = (const float*)d_in[11];
    const float* b_o       = (const float*)d_in[12];
    const float* ln2_s     = (const float*)d_in[13];
    const float* ln2_b     = (const float*)d_in[14];
    const float* W_ff1     = (const float*)d_in[15];
    const float* b_ff1     = (const float*)d_in[16];
    const float* W_ff2     = (const float*)d_in[17];
    const float* b_ff2     = (const float*)d_in[18];
    const float* W_gen     = (const float*)d_in[19];
    const float* b_gen     = (const float*)d_in[20];
    float* out = (float*)d_out;

    float *x, *xn, *qkv, *att, *mid;
    cudaGetSymbolAddress((void**)&x,   g_x);
    cudaGetSymbolAddress((void**)&xn,  g_xn);
    cudaGetSymbolAddress((void**)&qkv, g_qkv);
    cudaGetSymbolAddress((void**)&att, g_att);
    cudaGetSymbolAddress((void**)&mid, g_mid);

    embed_k<<<NTOK, DMODEL>>>(tokens, pos_idx, value_emb, coord_emb, pos_emb, x);

    for (int l = 0; l < NLAYER; l++) {
        const float* wqkv = W_qkv + (size_t)l * DMODEL * 3 * DMODEL;
        const float* bqkv = b_qkv + (size_t)l * 3 * DMODEL;
        const float* wo   = W_o   + (size_t)l * DMODEL * DMODEL;
        const float* bo   = b_o   + (size_t)l * DMODEL;
        const float* wf1  = W_ff1 + (size_t)l * DMODEL * 4 * DMODEL;
        const float* bf1  = b_ff1 + (size_t)l * 4 * DMODEL;
        const float* wf2  = W_ff2 + (size_t)l * 4 * DMODEL * DMODEL;
        const float* bf2  = b_ff2 + (size_t)l * DMODEL;

        ln_k<<<NTOK / 8, 256>>>(x, ln1_s + l * DMODEL, ln1_b + l * DMODEL, xn);

        { dim3 g(3 * DMODEL / 128, NTOK / 128);
          tgemm_k<0><<<g, 256>>>(xn, wqkv, bqkv, nullptr, qkv, NTOK, 3 * DMODEL, DMODEL); }

        attn_k<<<NBATCH * NHEAD, 384>>>(qkv, att);

        { dim3 g(DMODEL / 128, NTOK / 128);
          tgemm_k<2><<<g, 256>>>(att, wo, bo, x, x, NTOK, DMODEL, DMODEL); }

        ln_k<<<NTOK / 8, 256>>>(x, ln2_s + l * DMODEL, ln2_b + l * DMODEL, xn);

        { dim3 g(4 * DMODEL / 128, NTOK / 128);
          tgemm_k<1><<<g, 256>>>(xn, wf1, bf1, nullptr, mid, NTOK, 4 * DMODEL, DMODEL); }

        { dim3 g(DMODEL / 128, NTOK / 128);
          tgemm_k<2><<<g, 256>>>(mid, wf2, bf2, x, x, NTOK, DMODEL, 4 * DMODEL); }
    }

    { dim3 g(NVOCAB / 128, NTOK / 128);
      tgemm_k<0><<<g, 256>>>(x, W_gen, b_gen, nullptr, out, NTOK, NVOCAB, DMODEL); }

    lsm_k<<<NTOK, 256>>>(out);
}

// round 3
// speedup vs baseline: 3.1254x; 1.2416x over previous
#include <cuda_runtime.h>
#include <math.h>

#define NTOK 6144
#define DMODEL 256
#define NHEAD 8
#define DKH 32
#define NLAYER 2
#define NVOCAB 1024
#define LSEQ 96
#define NBATCH 64

// ---------------------------------------------------------------------------
// Scratch
// ---------------------------------------------------------------------------
__device__ float g_x  [NTOK * DMODEL];
__device__ float g_xn [NTOK * DMODEL];
__device__ float g_qkv[NTOK * 3 * DMODEL];
__device__ float g_att[NTOK * DMODEL];
__device__ float g_mid[NTOK * 4 * DMODEL];

// ---------------------------------------------------------------------------
// helpers
// ---------------------------------------------------------------------------
__device__ __forceinline__ void mma_tf32(float* c, unsigned a0, unsigned a1,
                                         unsigned a2, unsigned a3,
                                         unsigned b0, unsigned b1)
{
    asm volatile(
        "mma.sync.aligned.m16n8k8.row.col.f32.tf32.tf32.f32 "
        "{%0,%1,%2,%3}, {%4,%5,%6,%7}, {%8,%9}, {%0,%1,%2,%3};"
        : "+f"(c[0]), "+f"(c[1]), "+f"(c[2]), "+f"(c[3])
        : "r"(a0), "r"(a1), "r"(a2), "r"(a3), "r"(b0), "r"(b1));
}

__device__ __forceinline__ void cpa16(float* smem_dst, const float* gsrc)
{
    unsigned s = (unsigned)__cvta_generic_to_shared(smem_dst);
    asm volatile("cp.async.cg.shared.global [%0], [%1], 16;\n"
                 :: "r"(s), "l"(gsrc));
}
__device__ __forceinline__ void cpa_commit()
{
    asm volatile("cp.async.commit_group;\n" ::: "memory");
}
__device__ __forceinline__ void cpa_wait_all()
{
    asm volatile("cp.async.wait_group 0;\n" ::: "memory");
}

// ---------------------------------------------------------------------------
// Embedding
// ---------------------------------------------------------------------------
__global__ void embed_k(const int* __restrict__ tok, const int* __restrict__ pos,
                        const float* __restrict__ ve, const float* __restrict__ ce,
                        const float* __restrict__ pe, float* __restrict__ x)
{
    int n = blockIdx.x;
    int d = threadIdx.x;
    int p = pos[n];
    x[n * DMODEL + d] = ce[(p % 3) * DMODEL + d]
                      + pe[(p / 3) * DMODEL + d]
                      + ve[tok[n] * DMODEL + d];
}

// ---------------------------------------------------------------------------
// LayerNorm: one warp per row, float4 I/O, shfl reductions.
// ---------------------------------------------------------------------------
__global__ void ln_k(const float* __restrict__ x, const float* __restrict__ s,
                     const float* __restrict__ b, float* __restrict__ y)
{
    int row  = blockIdx.x * 8 + (threadIdx.x >> 5);
    int lane = threadIdx.x & 31;
    const float4* xr = (const float4*)(x + (size_t)row * DMODEL);
    float4 v0 = xr[lane];
    float4 v1 = xr[lane + 32];

    float sum = v0.x + v0.y + v0.z + v0.w + v1.x + v1.y + v1.z + v1.w;
    #pragma unroll
    for (int o = 16; o > 0; o >>= 1) sum += __shfl_xor_sync(0xffffffffu, sum, o);
    float mu = sum * (1.0f / DMODEL);

    float d0x=v0.x-mu, d0y=v0.y-mu, d0z=v0.z-mu, d0w=v0.w-mu;
    float d1x=v1.x-mu, d1y=v1.y-mu, d1z=v1.z-mu, d1w=v1.w-mu;
    float sq = d0x*d0x+d0y*d0y+d0z*d0z+d0w*d0w + d1x*d1x+d1y*d1y+d1z*d1z+d1w*d1w;
    #pragma unroll
    for (int o = 16; o > 0; o >>= 1) sq += __shfl_xor_sync(0xffffffffu, sq, o);
    float rs = rsqrtf(sq * (1.0f / DMODEL) + 1e-5f);

    const float4* sv = (const float4*)s;
    const float4* bv = (const float4*)b;
    float4* yr = (float4*)(y + (size_t)row * DMODEL);
    float4 s0 = sv[lane], s1 = sv[lane + 32];
    float4 b0 = bv[lane], b1 = bv[lane + 32];
    float4 o0, o1;
    o0.x = d0x*rs*s0.x + b0.x;  o0.y = d0y*rs*s0.y + b0.y;
    o0.z = d0z*rs*s0.z + b0.z;  o0.w = d0w*rs*s0.w + b0.w;
    o1.x = d1x*rs*s1.x + b1.x;  o1.y = d1y*rs*s1.y + b1.y;
    o1.z = d1z*rs*s1.z + b1.z;  o1.w = d1w*rs*s1.w + b1.w;
    yr[lane] = o0;
    yr[lane + 32] = o1;
}

// ---------------------------------------------------------------------------
// Tensor-core attention. One block (128 thr, 4 warps) per (batch, head).
// Phase 1: S = Q K^T via tf32 mma (Q,K in smem, warp w owns col-slab 24w..24w+24)
// exp+mask on fragments -> P staged in smem [96][100] (overlaid on Q/K).
// Phase 2: O = P V via tf32 mma; V B-fragments preloaded from gmem into regs.
// Fully-masked 16x8 tiles skipped in both phases.
// ---------------------------------------------------------------------------
__global__ __launch_bounds__(128)
void attn_k(const float* __restrict__ qkv, float* __restrict__ o)
{
    __shared__ float smb[96 * 100];      // phase1: Q at [r*36+c], K at 3456+[r*36+c]; phase2: P at [r*100+c]
    __shared__ float zpart[4][96];
    __shared__ float zinv[96];

    int bh = blockIdx.x;
    int b = bh >> 3, h = bh & 7;
    int base = b * LSEQ;
    int tid  = threadIdx.x;
    int lane = tid & 31, wid = tid >> 5;
    int g = lane >> 2, lt = lane & 3;

    const float* Qg = qkv + (size_t)base * (3 * DMODEL) + h * DKH;
    const float* Kg = Qg + DMODEL;
    const float* Vg = Qg + 2 * DMODEL;

    // preload V B-fragments for phase 2 (d-slab = 8*wid), hidden behind phase 1
    unsigned vreg[12][2];
    int d0 = 8 * wid;
    #pragma unroll
    for (int kt = 0; kt < 12; kt++) {
        vreg[kt][0] = __float_as_uint(Vg[(size_t)(8 * kt + lt)     * 768 + d0 + g]);
        vreg[kt][1] = __float_as_uint(Vg[(size_t)(8 * kt + lt + 4) * 768 + d0 + g]);
    }

    // stage Q,K into smem (padded stride 36 -> conflict-free fragment reads)
    for (int idx = tid; idx < 96 * 8; idx += 128) {
        int r = idx >> 3, q4 = (idx & 7) * 4;
        float4 qv = *(const float4*)(Qg + (size_t)r * 768 + q4);
        float4 kv = *(const float4*)(Kg + (size_t)r * 768 + q4);
        *(float4*)&smb[r * 36 + q4] = qv;
        *(float4*)&smb[3456 + r * 36 + q4] = kv;
    }
    __syncthreads();

    // ---- phase 1: S = Q K^T, warp w covers key-cols [24w, 24w+24) ----
    float acc[6][3][4];
    #pragma unroll
    for (int i = 0; i < 6; i++)
        #pragma unroll
        for (int j = 0; j < 3; j++)
            #pragma unroll
            for (int v = 0; v < 4; v++) acc[i][j][v] = 0.0f;

    int J0 = 3 * wid;
    #pragma unroll
    for (int kk = 0; kk < 32; kk += 8) {
        unsigned a[6][4];
        #pragma unroll
        for (int i = 0; i < 6; i++) {
            a[i][0] = __float_as_uint(smb[(16 * i + g)     * 36 + kk + lt]);
            a[i][1] = __float_as_uint(smb[(16 * i + 8 + g) * 36 + kk + lt]);
            a[i][2] = __float_as_uint(smb[(16 * i + g)     * 36 + kk + lt + 4]);
            a[i][3] = __float_as_uint(smb[(16 * i + 8 + g) * 36 + kk + lt + 4]);
        }
        #pragma unroll
        for (int jl = 0; jl < 3; jl++) {
            int J = J0 + jl;
            unsigned b0 = __float_as_uint(smb[3456 + (8 * J + g) * 36 + kk + lt]);
            unsigned b1 = __float_as_uint(smb[3456 + (8 * J + g) * 36 + kk + lt + 4]);
            #pragma unroll
            for (int i = 0; i < 6; i++)
                if (8 * J <= 16 * i + 15)   // skip fully-masked tiles
                    mma_tf32(acc[i][jl], a[i][0], a[i][1], a[i][2], a[i][3], b0, b1);
        }
    }
    __syncthreads();   // all Q/K reads done; smb becomes P

    // ---- exp + causal mask + write P + per-row z partials ----
    float zp[12];
    #pragma unroll
    for (int m = 0; m < 12; m++) zp[m] = 0.0f;
    const float invs = 0.17677669529663687f;   // 1/sqrt(32)

    #pragma unroll
    for (int i = 0; i < 6; i++) {
        int r0 = 16 * i + g, r1 = r0 + 8;
        #pragma unroll
        for (int jl = 0; jl < 3; jl++) {
            int J = J0 + jl;
            if (8 * J > 16 * i + 15) continue;       // unread region, skip
            int c = 8 * J + 2 * lt;
            float w0 = (c     <= r0) ? __expf(fminf(fmaxf(acc[i][jl][0] * invs, -5.0f), 5.0f)) : 0.0f;
            float w1 = (c + 1 <= r0) ? __expf(fminf(fmaxf(acc[i][jl][1] * invs, -5.0f), 5.0f)) : 0.0f;
            float w2 = (c     <= r1) ? __expf(fminf(fmaxf(acc[i][jl][2] * invs, -5.0f), 5.0f)) : 0.0f;
            float w3 = (c + 1 <= r1) ? __expf(fminf(fmaxf(acc[i][jl][3] * invs, -5.0f), 5.0f)) : 0.0f;
            zp[2 * i]     += w0 + w1;
            zp[2 * i + 1] += w2 + w3;
            float2 p0; p0.x = w0; p0.y = w1;
            float2 p1; p1.x = w2; p1.y = w3;
            *(float2*)&smb[r0 * 100 + c] = p0;
            *(float2*)&smb[r1 * 100 + c] = p1;
        }
    }
    // reduce z partials over the quad (lanes sharing a row)
    #pragma unroll
    for (int off = 1; off <= 2; off <<= 1)
        #pragma unroll
        for (int m = 0; m < 12; m++)
            zp[m] += __shfl_xor_sync(0xffffffffu, zp[m], off);
    if (lt == 0) {
        #pragma unroll
        for (int i = 0; i < 6; i++) {
            zpart[wid][16 * i + g]     = zp[2 * i];
            zpart[wid][16 * i + 8 + g] = zp[2 * i + 1];
        }
    }
    __syncthreads();
    if (tid < 96)
        zinv[tid] = 1.0f / (zpart[0][tid] + zpart[1][tid] + zpart[2][tid] + zpart[3][tid]);
    __syncthreads();

    // ---- phase 2: O = P V, warp w covers head-dims [8w, 8w+8) ----
    float oacc[6][4];
    #pragma unroll
    for (int i = 0; i < 6; i++)
        #pragma unroll
        for (int v = 0; v < 4; v++) oacc[i][v] = 0.0f;

    #pragma unroll
    for (int i = 0; i < 6; i++) {
        #pragma unroll
        for (int K2 = 0; K2 < 12; K2++) {
            if (K2 > 2 * i + 1) break;    // fully-masked k-tiles skipped
            unsigned a0 = __float_as_uint(smb[(16 * i + g)     * 100 + 8 * K2 + lt]);
            unsigned a1 = __float_as_uint(smb[(16 * i + 8 + g) * 100 + 8 * K2 + lt]);
            unsigned a2 = __float_as_uint(smb[(16 * i + g)     * 100 + 8 * K2 + lt + 4]);
            unsigned a3 = __float_as_uint(smb[(16 * i + 8 + g) * 100 + 8 * K2 + lt + 4]);
            mma_tf32(oacc[i], a0, a1, a2, a3, vreg[K2][0], vreg[K2][1]);
        }
    }

    // epilogue: divide by z, write
    #pragma unroll
    for (int i = 0; i < 6; i++) {
        int r0 = 16 * i + g, r1 = r0 + 8;
        float zi0 = zinv[r0], zi1 = zinv[r1];
        float2 v0, v1;
        v0.x = oacc[i][0] * zi0;  v0.y = oacc[i][1] * zi0;
        v1.x = oacc[i][2] * zi1;  v1.y = oacc[i][3] * zi1;
        *(float2*)(o + (size_t)(base + r0) * DMODEL + h * DKH + d0 + 2 * lt) = v0;
        *(float2*)(o + (size_t)(base + r1) * DMODEL + h * DKH + d0 + 2 * lt) = v1;
    }
}

// ---------------------------------------------------------------------------
// tf32 GEMM, cp.async 2-stage pipeline, raw fp32 fed to tensor cores
// (hardware truncates to tf32). BM x 128 tile, KT=16, 8 warps.
// OP 0: bias   OP 1: bias+relu   OP 2: bias+residual
// ---------------------------------------------------------------------------
template<int BM, int OP>
__global__ __launch_bounds__(256)
void tgemm_k(const float* __restrict__ A, const float* __restrict__ B,
             const float* __restrict__ bias, const float* __restrict__ res,
             float* __restrict__ C, int M, int N, int K)
{
    __shared__ float As[2][BM][20];
    __shared__ float Bs[2][16][136];

    constexpr int MW = (BM == 128) ? 4 : 2;   // warps along M
    constexpr int MI = (BM / MW) / 16;        // m16 tiles per warp (2)
    constexpr int NJ = (128 / (8 / MW)) / 8;  // n8 tiles per warp (8 or 4)

    int tid  = threadIdx.x;
    int lane = tid & 31, wid = tid >> 5;
    int g = lane >> 2, lt = lane & 3;
    int wm = (wid % MW) * (BM / MW);
    int wn = (wid / MW) * (128 / (8 / MW));
    int m0 = blockIdx.y * BM;
    int n0 = blockIdx.x * 128;

    // load geometry
    int ar = (BM == 128) ? (tid >> 2) : (tid >> 2);     // row within tile
    int aq = (tid & 3) * 4;
    int brr = tid >> 5;           // 0..7
    int bcc = (tid & 31) * 4;

    float acc[MI][NJ][4];
    #pragma unroll
    for (int i = 0; i < MI; i++)
        #pragma unroll
        for (int j = 0; j < NJ; j++)
            #pragma unroll
            for (int v = 0; v < 4; v++) acc[i][j][v] = 0.0f;

    int T = K >> 4;

    // ---- stage issue helper (as macro-ish lambda) ----
    auto issue = [&](int buf, int kt) {
        int k0 = kt * 16;
        if (BM == 128) {
            cpa16(&As[buf][ar][aq],        A + (size_t)(m0 + ar) * K + k0 + aq);
            cpa16(&As[buf][64 + ar][aq],   A + (size_t)(m0 + 64 + ar) * K + k0 + aq);
        } else {
            cpa16(&As[buf][ar][aq],        A + (size_t)(m0 + ar) * K + k0 + aq);
        }
        cpa16(&Bs[buf][brr][bcc],          B + (size_t)(k0 + brr) * N + n0 + bcc);
        cpa16(&Bs[buf][8 + brr][bcc],      B + (size_t)(k0 + 8 + brr) * N + n0 + bcc);
    };

    issue(0, 0);
    cpa_commit();

    for (int kt = 0; kt < T; kt++) {
        cpa_wait_all();
        __syncthreads();
        if (kt + 1 < T) {
            issue((kt + 1) & 1, kt + 1);
        }
        cpa_commit();

        int buf = kt & 1;
        #pragma unroll
        for (int kk = 0; kk < 16; kk += 8) {
            unsigned af[MI][4], bf[NJ][2];
            #pragma unroll
            for (int i = 0; i < MI; i++) {
                af[i][0] = __float_as_uint(As[buf][wm + 16 * i + g][kk + lt]);
                af[i][1] = __float_as_uint(As[buf][wm + 16 * i + g + 8][kk + lt]);
                af[i][2] = __float_as_uint(As[buf][wm + 16 * i + g][kk + lt + 4]);
                af[i][3] = __float_as_uint(As[buf][wm + 16 * i + g + 8][kk + lt + 4]);
            }
            #pragma unroll
            for (int j = 0; j < NJ; j++) {
                bf[j][0] = __float_as_uint(Bs[buf][kk + lt][wn + 8 * j + g]);
                bf[j][1] = __float_as_uint(Bs[buf][kk + lt + 4][wn + 8 * j + g]);
            }
            #pragma unroll
            for (int i = 0; i < MI; i++)
                #pragma unroll
                for (int j = 0; j < NJ; j++)
                    mma_tf32(acc[i][j], af[i][0], af[i][1], af[i][2], af[i][3],
                             bf[j][0], bf[j][1]);
        }
        __syncthreads();
    }

    // epilogue
    #pragma unroll
    for (int i = 0; i < MI; i++) {
        int r0 = m0 + wm + 16 * i + g;
        #pragma unroll
        for (int j = 0; j < NJ; j++) {
            int c = n0 + wn + 8 * j + 2 * lt;
            float bx = bias[c], by = bias[c + 1];
            float2 v0, v1;
            v0.x = acc[i][j][0] + bx;  v0.y = acc[i][j][1] + by;
            v1.x = acc[i][j][2] + bx;  v1.y = acc[i][j][3] + by;
            if (OP == 1) {
                v0.x = fmaxf(v0.x, 0.0f); v0.y = fmaxf(v0.y, 0.0f);
                v1.x = fmaxf(v1.x, 0.0f); v1.y = fmaxf(v1.y, 0.0f);
            }
            if (OP == 2) {
                float2 r0v = *(const float2*)(res + (size_t)r0 * N + c);
                float2 r1v = *(const float2*)(res + (size_t)(r0 + 8) * N + c);
                v0.x += r0v.x; v0.y += r0v.y;
                v1.x += r1v.x; v1.y += r1v.y;
            }
            *(float2*)(C + (size_t)r0 * N + c) = v0;
            *(float2*)(C + (size_t)(r0 + 8) * N + c) = v1;
        }
    }
}

// ---------------------------------------------------------------------------
// In-place log_softmax over VOCAB=1024
// ---------------------------------------------------------------------------
__global__ void lsm_k(float* __restrict__ out)
{
    __shared__ float red[256];
    int n = blockIdx.x, t = threadIdx.x;
    float v[4];
    #pragma unroll
    for (int j = 0; j < 4; j++) v[j] = out[(size_t)n * NVOCAB + t + j * 256];

    float m = fmaxf(fmaxf(v[0], v[1]), fmaxf(v[2], v[3]));
    red[t] = m;
    __syncthreads();
    #pragma unroll
    for (int o = 128; o > 0; o >>= 1) {
        if (t < o) red[t] = fmaxf(red[t], red[t + o]);
        __syncthreads();
    }
    float M = red[0];
    __syncthreads();

    float s = 0.0f;
    #pragma unroll
    for (int j = 0; j < 4; j++) s += __expf(v[j] - M);
    red[t] = s;
    __syncthreads();
    #pragma unroll
    for (int o = 128; o > 0; o >>= 1) {
        if (t < o) red[t] += red[t + o];
        __syncthreads();
    }
    float lse = M + __logf(red[0]);

    #pragma unroll
    for (int j = 0; j < 4; j++)
        out[(size_t)n * NVOCAB + t + j * 256] = v[j] - lse;
}

// ---------------------------------------------------------------------------
// Launch
// ---------------------------------------------------------------------------
extern "C" void kernel_launch(void* const* d_in, const int* in_sizes, int n_in,
                              void* d_out, int out_size)
{
    const int*   tokens    = (const int*)  d_in[0];
    const int*   pos_idx   = (const int*)  d_in[1];
    const float* value_emb = (const float*)d_in[4];
    const float* coord_emb = (const float*)d_in[5];
    const float* pos_emb   = (const float*)d_in[6];
    const float* ln1_s     = (const float*)d_in[7];
    const float* ln1_b     = (const float*)d_in[8];
    const float* W_qkv     = (const float*)d_in[9];
    const float* b_qkv     = (const float*)d_in[10];
    const float* W_o       = (const float*)d_in[11];
    const float* b_o       = (const float*)d_in[12];
    const float* ln2_s     = (const float*)d_in[13];
    const float* ln2_b     = (const float*)d_in[14];
    const float* W_ff1     = (const float*)d_in[15];
    const float* b_ff1     = (const float*)d_in[16];
    const float* W_ff2     = (const float*)d_in[17];
    const float* b_ff2     = (const float*)d_in[18];
    const float* W_gen     = (const float*)d_in[19];
    const float* b_gen     = (const float*)d_in[20];
    float* out = (float*)d_out;

    float *x, *xn, *qkv, *att, *mid;
    cudaGetSymbolAddress((void**)&x,   g_x);
    cudaGetSymbolAddress((void**)&xn,  g_xn);
    cudaGetSymbolAddress((void**)&qkv, g_qkv);
    cudaGetSymbolAddress((void**)&att, g_att);
    cudaGetSymbolAddress((void**)&mid, g_mid);

    embed_k<<<NTOK, DMODEL>>>(tokens, pos_idx, value_emb, coord_emb, pos_emb, x);

    for (int l = 0; l < NLAYER; l++) {
        const float* wqkv = W_qkv + (size_t)l * DMODEL * 3 * DMODEL;
        const float* bqkv = b_qkv + (size_t)l * 3 * DMODEL;
        const float* wo   = W_o   + (size_t)l * DMODEL * DMODEL;
        const float* bo   = b_o   + (size_t)l * DMODEL;
        const float* wf1  = W_ff1 + (size_t)l * DMODEL * 4 * DMODEL;
        const float* bf1  = b_ff1 + (size_t)l * 4 * DMODEL;
        const float* wf2  = W_ff2 + (size_t)l * 4 * DMODEL * DMODEL;
        const float* bf2  = b_ff2 + (size_t)l * DMODEL;

        ln_k<<<NTOK / 8, 256>>>(x, ln1_s + l * DMODEL, ln1_b + l * DMODEL, xn);

        { dim3 g(3 * DMODEL / 128, NTOK / 128);
          tgemm_k<128, 0><<<g, 256>>>(xn, wqkv, bqkv, nullptr, qkv, NTOK, 3 * DMODEL, DMODEL); }

        attn_k<<<NBATCH * NHEAD, 128>>>(qkv, att);

        { dim3 g(DMODEL / 128, NTOK / 64);
          tgemm_k<64, 2><<<g, 256>>>(att, wo, bo, x, x, NTOK, DMODEL, DMODEL); }

        ln_k<<<NTOK / 8, 256>>>(x, ln2_s + l * DMODEL, ln2_b + l * DMODEL, xn);

        { dim3 g(4 * DMODEL / 128, NTOK / 128);
          tgemm_k<128, 1><<<g, 256>>>(xn, wf1, bf1, nullptr, mid, NTOK, 4 * DMODEL, DMODEL); }

        { dim3 g(DMODEL / 128, NTOK / 64);
          tgemm_k<64, 2><<<g, 256>>>(mid, wf2, bf2, x, x, NTOK, DMODEL, 4 * DMODEL); }
    }

    { dim3 g(NVOCAB / 128, NTOK / 128);
      tgemm_k<128, 0><<<g, 256>>>(x, W_gen, b_gen, nullptr, out, NTOK, NVOCAB, DMODEL); }

    lsm_k<<<NTOK, 256>>>(out);
}

// round 4
// speedup vs baseline: 3.9840x; 1.2747x over previous
#include <cuda_runtime.h>
#include <cuda_bf16.h>
#include <math.h>

#define NTOK 6144
#define DMODEL 256
#define NHEAD 8
#define DKH 32
#define NLAYER 2
#define NVOCAB 1024
#define LSEQ 96
#define NBATCH 64

typedef __nv_bfloat16 bf16;
typedef __nv_bfloat162 bf162;

// ---------------------------------------------------------------------------
// Scratch
// ---------------------------------------------------------------------------
__device__ float g_x  [NTOK * DMODEL];            // fp32 residual stream
__device__ float g_qkv[NTOK * 3 * DMODEL];        // fp32 qkv (attn input)
__device__ bf16  g_xn [NTOK * DMODEL];            // bf16 LN output
__device__ bf16  g_att[NTOK * DMODEL];            // bf16 attention output
__device__ bf16  g_mid[NTOK * 4 * DMODEL];        // bf16 FFN hidden
__device__ bf16  g_xb [NTOK * DMODEL];            // bf16 copy of x (gen input)
// bf16 weights
__device__ bf16 g_wqkv[NLAYER * DMODEL * 3 * DMODEL];
__device__ bf16 g_wo  [NLAYER * DMODEL * DMODEL];
__device__ bf16 g_wf1 [NLAYER * DMODEL * 4 * DMODEL];
__device__ bf16 g_wf2 [NLAYER * 4 * DMODEL * DMODEL];
__device__ bf16 g_wgen[DMODEL * NVOCAB];

// ---------------------------------------------------------------------------
// helpers
// ---------------------------------------------------------------------------
__device__ __forceinline__ unsigned pk2(float a, float b)
{
    bf162 t = __floats2bfloat162_rn(a, b);
    return *(unsigned*)&t;
}

__device__ __forceinline__ void mma_tf32(float* c, unsigned a0, unsigned a1,
                                         unsigned a2, unsigned a3,
                                         unsigned b0, unsigned b1)
{
    asm volatile(
        "mma.sync.aligned.m16n8k8.row.col.f32.tf32.tf32.f32 "
        "{%0,%1,%2,%3}, {%4,%5,%6,%7}, {%8,%9}, {%0,%1,%2,%3};"
        : "+f"(c[0]), "+f"(c[1]), "+f"(c[2]), "+f"(c[3])
        : "r"(a0), "r"(a1), "r"(a2), "r"(a3), "r"(b0), "r"(b1));
}

__device__ __forceinline__ void mma_bf16(float* c, unsigned a0, unsigned a1,
                                         unsigned a2, unsigned a3,
                                         unsigned b0, unsigned b1)
{
    asm volatile(
        "mma.sync.aligned.m16n8k16.row.col.f32.bf16.bf16.f32 "
        "{%0,%1,%2,%3}, {%4,%5,%6,%7}, {%8,%9}, {%0,%1,%2,%3};"
        : "+f"(c[0]), "+f"(c[1]), "+f"(c[2]), "+f"(c[3])
        : "r"(a0), "r"(a1), "r"(a2), "r"(a3), "r"(b0), "r"(b1));
}

__device__ __forceinline__ void ldsm4(unsigned& r0, unsigned& r1,
                                      unsigned& r2, unsigned& r3, const void* p)
{
    unsigned a = (unsigned)__cvta_generic_to_shared(p);
    asm volatile("ldmatrix.sync.aligned.m8n8.x4.shared.b16 {%0,%1,%2,%3}, [%4];"
                 : "=r"(r0), "=r"(r1), "=r"(r2), "=r"(r3) : "r"(a));
}

__device__ __forceinline__ void ldsm4t(unsigned& r0, unsigned& r1,
                                       unsigned& r2, unsigned& r3, const void* p)
{
    unsigned a = (unsigned)__cvta_generic_to_shared(p);
    asm volatile("ldmatrix.sync.aligned.m8n8.x4.trans.shared.b16 {%0,%1,%2,%3}, [%4];"
                 : "=r"(r0), "=r"(r1), "=r"(r2), "=r"(r3) : "r"(a));
}

__device__ __forceinline__ void cpa16(void* smem_dst, const void* gsrc)
{
    unsigned s = (unsigned)__cvta_generic_to_shared(smem_dst);
    asm volatile("cp.async.cg.shared.global [%0], [%1], 16;\n" :: "r"(s), "l"(gsrc));
}
__device__ __forceinline__ void cpa_commit()
{
    asm volatile("cp.async.commit_group;\n" ::: "memory");
}
__device__ __forceinline__ void cpa_wait_all()
{
    asm volatile("cp.async.wait_group 0;\n" ::: "memory");
}

// ---------------------------------------------------------------------------
// fp32 -> bf16 weight conversion (vectorized, per tensor)
// ---------------------------------------------------------------------------
__global__ void cvt_k(const float4* __restrict__ src, uint2* __restrict__ dst, int n4)
{
    int i = blockIdx.x * 256 + threadIdx.x;
    if (i < n4) {
        float4 v = src[i];
        uint2 u;
        u.x = pk2(v.x, v.y);
        u.y = pk2(v.z, v.w);
        dst[i] = u;
    }
}

// ---------------------------------------------------------------------------
// Embedding
// ---------------------------------------------------------------------------
__global__ void embed_k(const int* __restrict__ tok, const int* __restrict__ pos,
                        const float* __restrict__ ve, const float* __restrict__ ce,
                        const float* __restrict__ pe, float* __restrict__ x)
{
    int n = blockIdx.x;
    int d = threadIdx.x;
    int p = pos[n];
    x[n * DMODEL + d] = ce[(p % 3) * DMODEL + d]
                      + pe[(p / 3) * DMODEL + d]
                      + ve[tok[n] * DMODEL + d];
}

// ---------------------------------------------------------------------------
// LayerNorm: one warp per row, fp32 in, bf16 out
// ---------------------------------------------------------------------------
__global__ void ln_k(const float* __restrict__ x, const float* __restrict__ s,
                     const float* __restrict__ b, bf16* __restrict__ y)
{
    int row  = blockIdx.x * 8 + (threadIdx.x >> 5);
    int lane = threadIdx.x & 31;
    const float4* xr = (const float4*)(x + (size_t)row * DMODEL);
    float4 v0 = xr[lane];
    float4 v1 = xr[lane + 32];

    float sum = v0.x + v0.y + v0.z + v0.w + v1.x + v1.y + v1.z + v1.w;
    #pragma unroll
    for (int o = 16; o > 0; o >>= 1) sum += __shfl_xor_sync(0xffffffffu, sum, o);
    float mu = sum * (1.0f / DMODEL);

    float d0x=v0.x-mu, d0y=v0.y-mu, d0z=v0.z-mu, d0w=v0.w-mu;
    float d1x=v1.x-mu, d1y=v1.y-mu, d1z=v1.z-mu, d1w=v1.w-mu;
    float sq = d0x*d0x+d0y*d0y+d0z*d0z+d0w*d0w + d1x*d1x+d1y*d1y+d1z*d1z+d1w*d1w;
    #pragma unroll
    for (int o = 16; o > 0; o >>= 1) sq += __shfl_xor_sync(0xffffffffu, sq, o);
    float rs = rsqrtf(sq * (1.0f / DMODEL) + 1e-5f);

    const float4* sv = (const float4*)s;
    const float4* bv = (const float4*)b;
    float4 s0 = sv[lane], s1 = sv[lane + 32];
    float4 b0 = bv[lane], b1 = bv[lane + 32];
    uint2 u0, u1;
    u0.x = pk2(d0x*rs*s0.x + b0.x, d0y*rs*s0.y + b0.y);
    u0.y = pk2(d0z*rs*s0.z + b0.z, d0w*rs*s0.w + b0.w);
    u1.x = pk2(d1x*rs*s1.x + b1.x, d1y*rs*s1.y + b1.y);
    u1.y = pk2(d1z*rs*s1.z + b1.z, d1w*rs*s1.w + b1.w);
    *(uint2*)(y + (size_t)row * DMODEL + lane * 4)        = u0;
    *(uint2*)(y + (size_t)row * DMODEL + (lane + 32) * 4) = u1;
}

// ---------------------------------------------------------------------------
// Tensor-core attention (tf32), bf16 output. One block per (batch, head).
// ---------------------------------------------------------------------------
__global__ __launch_bounds__(128)
void attn_k(const float* __restrict__ qkv, bf16* __restrict__ o)
{
    __shared__ float smb[96 * 100];
    __shared__ float zpart[4][96];
    __shared__ float zinv[96];

    int bh = blockIdx.x;
    int b = bh >> 3, h = bh & 7;
    int base = b * LSEQ;
    int tid  = threadIdx.x;
    int lane = tid & 31, wid = tid >> 5;
    int g = lane >> 2, lt = lane & 3;

    const float* Qg = qkv + (size_t)base * (3 * DMODEL) + h * DKH;
    const float* Kg = Qg + DMODEL;
    const float* Vg = Qg + 2 * DMODEL;

    unsigned vreg[12][2];
    int d0 = 8 * wid;
    #pragma unroll
    for (int kt = 0; kt < 12; kt++) {
        vreg[kt][0] = __float_as_uint(Vg[(size_t)(8 * kt + lt)     * 768 + d0 + g]);
        vreg[kt][1] = __float_as_uint(Vg[(size_t)(8 * kt + lt + 4) * 768 + d0 + g]);
    }

    for (int idx = tid; idx < 96 * 8; idx += 128) {
        int r = idx >> 3, q4 = (idx & 7) * 4;
        float4 qv = *(const float4*)(Qg + (size_t)r * 768 + q4);
        float4 kv = *(const float4*)(Kg + (size_t)r * 768 + q4);
        *(float4*)&smb[r * 36 + q4] = qv;
        *(float4*)&smb[3456 + r * 36 + q4] = kv;
    }
    __syncthreads();

    float acc[6][3][4];
    #pragma unroll
    for (int i = 0; i < 6; i++)
        #pragma unroll
        for (int j = 0; j < 3; j++)
            #pragma unroll
            for (int v = 0; v < 4; v++) acc[i][j][v] = 0.0f;

    int J0 = 3 * wid;
    #pragma unroll
    for (int kk = 0; kk < 32; kk += 8) {
        unsigned a[6][4];
        #pragma unroll
        for (int i = 0; i < 6; i++) {
            a[i][0] = __float_as_uint(smb[(16 * i + g)     * 36 + kk + lt]);
            a[i][1] = __float_as_uint(smb[(16 * i + 8 + g) * 36 + kk + lt]);
            a[i][2] = __float_as_uint(smb[(16 * i + g)     * 36 + kk + lt + 4]);
            a[i][3] = __float_as_uint(smb[(16 * i + 8 + g) * 36 + kk + lt + 4]);
        }
        #pragma unroll
        for (int jl = 0; jl < 3; jl++) {
            int J = J0 + jl;
            unsigned b0 = __float_as_uint(smb[3456 + (8 * J + g) * 36 + kk + lt]);
            unsigned b1 = __float_as_uint(smb[3456 + (8 * J + g) * 36 + kk + lt + 4]);
            #pragma unroll
            for (int i = 0; i < 6; i++)
                if (8 * J <= 16 * i + 15)
                    mma_tf32(acc[i][jl], a[i][0], a[i][1], a[i][2], a[i][3], b0, b1);
        }
    }
    __syncthreads();

    float zp[12];
    #pragma unroll
    for (int m = 0; m < 12; m++) zp[m] = 0.0f;
    const float invs = 0.17677669529663687f;

    #pragma unroll
    for (int i = 0; i < 6; i++) {
        int r0 = 16 * i + g, r1 = r0 + 8;
        #pragma unroll
        for (int jl = 0; jl < 3; jl++) {
            int J = J0 + jl;
            if (8 * J > 16 * i + 15) continue;
            int c = 8 * J + 2 * lt;
            float w0 = (c     <= r0) ? __expf(fminf(fmaxf(acc[i][jl][0] * invs, -5.0f), 5.0f)) : 0.0f;
            float w1 = (c + 1 <= r0) ? __expf(fminf(fmaxf(acc[i][jl][1] * invs, -5.0f), 5.0f)) : 0.0f;
            float w2 = (c     <= r1) ? __expf(fminf(fmaxf(acc[i][jl][2] * invs, -5.0f), 5.0f)) : 0.0f;
            float w3 = (c + 1 <= r1) ? __expf(fminf(fmaxf(acc[i][jl][3] * invs, -5.0f), 5.0f)) : 0.0f;
            zp[2 * i]     += w0 + w1;
            zp[2 * i + 1] += w2 + w3;
            float2 p0; p0.x = w0; p0.y = w1;
            float2 p1; p1.x = w2; p1.y = w3;
            *(float2*)&smb[r0 * 100 + c] = p0;
            *(float2*)&smb[r1 * 100 + c] = p1;
        }
    }
    #pragma unroll
    for (int off = 1; off <= 2; off <<= 1)
        #pragma unroll
        for (int m = 0; m < 12; m++)
            zp[m] += __shfl_xor_sync(0xffffffffu, zp[m], off);
    if (lt == 0) {
        #pragma unroll
        for (int i = 0; i < 6; i++) {
            zpart[wid][16 * i + g]     = zp[2 * i];
            zpart[wid][16 * i + 8 + g] = zp[2 * i + 1];
        }
    }
    __syncthreads();
    if (tid < 96)
        zinv[tid] = 1.0f / (zpart[0][tid] + zpart[1][tid] + zpart[2][tid] + zpart[3][tid]);
    __syncthreads();

    float oacc[6][4];
    #pragma unroll
    for (int i = 0; i < 6; i++)
        #pragma unroll
        for (int v = 0; v < 4; v++) oacc[i][v] = 0.0f;

    #pragma unroll
    for (int i = 0; i < 6; i++) {
        #pragma unroll
        for (int K2 = 0; K2 < 12; K2++) {
            if (K2 > 2 * i + 1) break;
            unsigned a0 = __float_as_uint(smb[(16 * i + g)     * 100 + 8 * K2 + lt]);
            unsigned a1 = __float_as_uint(smb[(16 * i + 8 + g) * 100 + 8 * K2 + lt]);
            unsigned a2 = __float_as_uint(smb[(16 * i + g)     * 100 + 8 * K2 + lt + 4]);
            unsigned a3 = __float_as_uint(smb[(16 * i + 8 + g) * 100 + 8 * K2 + lt + 4]);
            mma_tf32(oacc[i], a0, a1, a2, a3, vreg[K2][0], vreg[K2][1]);
        }
    }

    #pragma unroll
    for (int i = 0; i < 6; i++) {
        int r0 = 16 * i + g, r1 = r0 + 8;
        float zi0 = zinv[r0], zi1 = zinv[r1];
        unsigned u0 = pk2(oacc[i][0] * zi0, oacc[i][1] * zi0);
        unsigned u1 = pk2(oacc[i][2] * zi1, oacc[i][3] * zi1);
        *(unsigned*)(o + (size_t)(base + r0) * DMODEL + h * DKH + d0 + 2 * lt) = u0;
        *(unsigned*)(o + (size_t)(base + r1) * DMODEL + h * DKH + d0 + 2 * lt) = u1;
    }
}

// ---------------------------------------------------------------------------
// bf16 tensor-core GEMM: C = A[M,K] @ B[K,N] + bias (+relu/+residual)
// BM x 128 tile, KT=16, cp.async double buffer, ldmatrix + mma.m16n8k16.
// OP: 0 bias, 1 bias+relu, 2 bias+residual
// OUTM: bit0 -> write fp32 C, bit1 -> write bf16 Cb
// ---------------------------------------------------------------------------
template<int BM, int OP, int OUTM>
__global__ __launch_bounds__(256)
void hgemm_k(const bf16* __restrict__ A, const bf16* __restrict__ B,
             const float* __restrict__ bias, const float* __restrict__ res,
             float* __restrict__ C, bf16* __restrict__ Cb,
             int M, int N, int K)
{
    constexpr int AST = 24;    // As row stride (bf16): 48 B, conflict-free ldmatrix
    constexpr int BST = 136;   // Bs row stride (bf16): 272 B, conflict-free ldmatrix
    __shared__ bf16 As[2][BM][AST];
    __shared__ bf16 Bs[2][16][BST];

    constexpr int MW = (BM == 128) ? 4 : 2;  // warps along M
    constexpr int WN = 128 / (8 / MW);       // warp tile N: 64 or 32
    constexpr int MI = (BM / MW) / 16;       // 2
    constexpr int NJ = WN / 8;               // 8 or 4

    int tid  = threadIdx.x;
    int lane = tid & 31, wid = tid >> 5;
    int g = lane >> 2, lt = lane & 3;
    int wm = (wid % MW) * (BM / MW);
    int wn = (wid / MW) * WN;
    int m0 = blockIdx.y * BM;
    int n0 = blockIdx.x * 128;

    // cp.async geometry
    int ar   = tid >> 1;           // A row (0..127)
    int ah   = (tid & 1) * 8;      // 8-bf16 chunk within k-tile
    int brow = tid >> 4;           // B row (0..15)
    int bc8  = (tid & 15) * 8;     // 8-bf16 chunk along n

    // ldmatrix per-lane addressing
    int ltile = lane >> 3, lr = lane & 7;
    int a_roff = (ltile & 1) * 8 + lr;      // row offset within 16-row tile
    int a_koff = (ltile >> 1) * 8;          // k offset
    int b_roff = (ltile & 1) * 8 + lr;      // k row within 16
    int b_coff = (ltile >> 1) * 8;          // n offset within 16-col pair

    float acc[MI][NJ][4];
    #pragma unroll
    for (int i = 0; i < MI; i++)
        #pragma unroll
        for (int j = 0; j < NJ; j++)
            #pragma unroll
            for (int v = 0; v < 4; v++) acc[i][j][v] = 0.0f;

    int T = K >> 4;

    auto issue = [&](int buf, int kt) {
        int k0 = kt * 16;
        if (BM == 128 || tid < 128)
            cpa16(&As[buf][ar][ah], A + (size_t)(m0 + ar) * K + k0 + ah);
        cpa16(&Bs[buf][brow][bc8], B + (size_t)(k0 + brow) * N + n0 + bc8);
    };

    issue(0, 0);
    cpa_commit();

    for (int kt = 0; kt < T; kt++) {
        cpa_wait_all();
        __syncthreads();
        if (kt + 1 < T) issue((kt + 1) & 1, kt + 1);
        cpa_commit();

        int buf = kt & 1;
        unsigned af[MI][4], bf[NJ][2];
        #pragma unroll
        for (int i = 0; i < MI; i++)
            ldsm4(af[i][0], af[i][1], af[i][2], af[i][3],
                  &As[buf][wm + 16 * i + a_roff][a_koff]);
        #pragma unroll
        for (int jp = 0; jp < NJ / 2; jp++) {
            unsigned r0, r1, r2, r3;
            ldsm4t(r0, r1, r2, r3, &Bs[buf][b_roff][wn + 16 * jp + b_coff]);
            bf[2 * jp][0] = r0;  bf[2 * jp][1] = r1;
            bf[2 * jp + 1][0] = r2;  bf[2 * jp + 1][1] = r3;
        }
        #pragma unroll
        for (int i = 0; i < MI; i++)
            #pragma unroll
            for (int j = 0; j < NJ; j++)
                mma_bf16(acc[i][j], af[i][0], af[i][1], af[i][2], af[i][3],
                         bf[j][0], bf[j][1]);
        __syncthreads();
    }

    // epilogue
    #pragma unroll
    for (int i = 0; i < MI; i++) {
        int r0 = m0 + wm + 16 * i + g;
        #pragma unroll
        for (int j = 0; j < NJ; j++) {
            int c = n0 + wn + 8 * j + 2 * lt;
            float bx = bias[c], by = bias[c + 1];
            float2 v0, v1;
            v0.x = acc[i][j][0] + bx;  v0.y = acc[i][j][1] + by;
            v1.x = acc[i][j][2] + bx;  v1.y = acc[i][j][3] + by;
            if (OP == 1) {
                v0.x = fmaxf(v0.x, 0.0f); v0.y = fmaxf(v0.y, 0.0f);
                v1.x = fmaxf(v1.x, 0.0f); v1.y = fmaxf(v1.y, 0.0f);
            }
            if (OP == 2) {
                float2 r0v = *(const float2*)(res + (size_t)r0 * N + c);
                float2 r1v = *(const float2*)(res + (size_t)(r0 + 8) * N + c);
                v0.x += r0v.x; v0.y += r0v.y;
                v1.x += r1v.x; v1.y += r1v.y;
            }
            if (OUTM & 1) {
                *(float2*)(C + (size_t)r0 * N + c) = v0;
                *(float2*)(C + (size_t)(r0 + 8) * N + c) = v1;
            }
            if (OUTM & 2) {
                *(unsigned*)(Cb + (size_t)r0 * N + c) = pk2(v0.x, v0.y);
                *(unsigned*)(Cb + (size_t)(r0 + 8) * N + c) = pk2(v1.x, v1.y);
            }
        }
    }
}

// ---------------------------------------------------------------------------
// In-place log_softmax over VOCAB=1024
// ---------------------------------------------------------------------------
__global__ void lsm_k(float* __restrict__ out)
{
    __shared__ float red[256];
    int n = blockIdx.x, t = threadIdx.x;
    float v[4];
    #pragma unroll
    for (int j = 0; j < 4; j++) v[j] = out[(size_t)n * NVOCAB + t + j * 256];

    float m = fmaxf(fmaxf(v[0], v[1]), fmaxf(v[2], v[3]));
    red[t] = m;
    __syncthreads();
    #pragma unroll
    for (int o = 128; o > 0; o >>= 1) {
        if (t < o) red[t] = fmaxf(red[t], red[t + o]);
        __syncthreads();
    }
    float M = red[0];
    __syncthreads();

    float s = 0.0f;
    #pragma unroll
    for (int j = 0; j < 4; j++) s += __expf(v[j] - M);
    red[t] = s;
    __syncthreads();
    #pragma unroll
    for (int o = 128; o > 0; o >>= 1) {
        if (t < o) red[t] += red[t + o];
        __syncthreads();
    }
    float lse = M + __logf(red[0]);

    #pragma unroll
    for (int j = 0; j < 4; j++)
        out[(size_t)n * NVOCAB + t + j * 256] = v[j] - lse;
}

// ---------------------------------------------------------------------------
// Launch
// ---------------------------------------------------------------------------
extern "C" void kernel_launch(void* const* d_in, const int* in_sizes, int n_in,
                              void* d_out, int out_size)
{
    const int*   tokens    = (const int*)  d_in[0];
    const int*   pos_idx   = (const int*)  d_in[1];
    const float* value_emb = (const float*)d_in[4];
    const float* coord_emb = (const float*)d_in[5];
    const float* pos_emb   = (const float*)d_in[6];
    const float* ln1_s     = (const float*)d_in[7];
    const float* ln1_b     = (const float*)d_in[8];
    const float* W_qkv     = (const float*)d_in[9];
    const float* b_qkv     = (const float*)d_in[10];
    const float* W_o       = (const float*)d_in[11];
    const float* b_o       = (const float*)d_in[12];
    const float* ln2_s     = (const float*)d_in[13];
    const float* ln2_b     = (const float*)d_in[14];
    const float* W_ff1     = (const float*)d_in[15];
    const float* b_ff1     = (const float*)d_in[16];
    const float* W_ff2     = (const float*)d_in[17];
    const float* b_ff2     = (const float*)d_in[18];
    const float* W_gen     = (const float*)d_in[19];
    const float* b_gen     = (const float*)d_in[20];
    float* out = (float*)d_out;

    float *x, *qkv;
    bf16 *xn, *att, *mid, *xb;
    bf16 *wqkvb, *wob, *wf1b, *wf2b, *wgenb;
    cudaGetSymbolAddress((void**)&x,    g_x);
    cudaGetSymbolAddress((void**)&qkv,  g_qkv);
    cudaGetSymbolAddress((void**)&xn,   g_xn);
    cudaGetSymbolAddress((void**)&att,  g_att);
    cudaGetSymbolAddress((void**)&mid,  g_mid);
    cudaGetSymbolAddress((void**)&xb,   g_xb);
    cudaGetSymbolAddress((void**)&wqkvb, g_wqkv);
    cudaGetSymbolAddress((void**)&wob,   g_wo);
    cudaGetSymbolAddress((void**)&wf1b,  g_wf1);
    cudaGetSymbolAddress((void**)&wf2b,  g_wf2);
    cudaGetSymbolAddress((void**)&wgenb, g_wgen);

    // weight conversions (once per launch)
    { int n4 = NLAYER * DMODEL * 3 * DMODEL / 4;
      cvt_k<<<(n4 + 255) / 256, 256>>>((const float4*)W_qkv, (uint2*)wqkvb, n4); }
    { int n4 = NLAYER * DMODEL * DMODEL / 4;
      cvt_k<<<(n4 + 255) / 256, 256>>>((const float4*)W_o, (uint2*)wob, n4); }
    { int n4 = NLAYER * DMODEL * 4 * DMODEL / 4;
      cvt_k<<<(n4 + 255) / 256, 256>>>((const float4*)W_ff1, (uint2*)wf1b, n4); }
    { int n4 = NLAYER * 4 * DMODEL * DMODEL / 4;
      cvt_k<<<(n4 + 255) / 256, 256>>>((const float4*)W_ff2, (uint2*)wf2b, n4); }
    { int n4 = DMODEL * NVOCAB / 4;
      cvt_k<<<(n4 + 255) / 256, 256>>>((const float4*)W_gen, (uint2*)wgenb, n4); }

    embed_k<<<NTOK, DMODEL>>>(tokens, pos_idx, value_emb, coord_emb, pos_emb, x);

    for (int l = 0; l < NLAYER; l++) {
        const bf16* wqkv = wqkvb + (size_t)l * DMODEL * 3 * DMODEL;
        const float* bqkv = b_qkv + (size_t)l * 3 * DMODEL;
        const bf16* wo    = wob   + (size_t)l * DMODEL * DMODEL;
        const float* bo   = b_o   + (size_t)l * DMODEL;
        const bf16* wf1   = wf1b  + (size_t)l * DMODEL * 4 * DMODEL;
        const float* bf1  = b_ff1 + (size_t)l * 4 * DMODEL;
        const bf16* wf2   = wf2b  + (size_t)l * 4 * DMODEL * DMODEL;
        const float* bf2  = b_ff2 + (size_t)l * DMODEL;

        ln_k<<<NTOK / 8, 256>>>(x, ln1_s + l * DMODEL, ln1_b + l * DMODEL, xn);

        { dim3 g(3 * DMODEL / 128, NTOK / 128);
          hgemm_k<128, 0, 1><<<g, 256>>>(xn, wqkv, bqkv, nullptr, qkv, nullptr,
                                         NTOK, 3 * DMODEL, DMODEL); }

        attn_k<<<NBATCH * NHEAD, 128>>>(qkv, att);

        { dim3 g(DMODEL / 128, NTOK / 64);
          hgemm_k<64, 2, 1><<<g, 256>>>(att, wo, bo, x, x, nullptr,
                                        NTOK, DMODEL, DMODEL); }

        ln_k<<<NTOK / 8, 256>>>(x, ln2_s + l * DMODEL, ln2_b + l * DMODEL, xn);

        { dim3 g(4 * DMODEL / 128, NTOK / 128);
          hgemm_k<128, 1, 2><<<g, 256>>>(xn, wf1, bf1, nullptr, nullptr, mid,
                                         NTOK, 4 * DMODEL, DMODEL); }

        { dim3 g(DMODEL / 128, NTOK / 64);
          hgemm_k<64, 2, 3><<<g, 256>>>(mid, wf2, bf2, x, x, xb,
                                        NTOK, DMODEL, 4 * DMODEL); }
    }

    { dim3 g(NVOCAB / 128, NTOK / 128);
      hgemm_k<128, 0, 1><<<g, 256>>>(xb, wgenb, b_gen, nullptr, out, nullptr,
                                     NTOK, NVOCAB, DMODEL); }

    lsm_k<<<NTOK, 256>>>(out);
}

// round 5
// speedup vs baseline: 5.1384x; 1.2897x over previous
#include <cuda_runtime.h>
#include <cuda_bf16.h>
#include <math.h>

#define NTOK 6144
#define DMODEL 256
#define NHEAD 8
#define DKH 32
#define NLAYER 2
#define NVOCAB 1024
#define LSEQ 96
#define NBATCH 64

typedef __nv_bfloat16 bf16;
typedef __nv_bfloat162 bf162;

// ---------------------------------------------------------------------------
// Scratch
// ---------------------------------------------------------------------------
__device__ float g_x  [NTOK * DMODEL];
__device__ float g_qkv[NTOK * 3 * DMODEL];
__device__ bf16  g_xn [NTOK * DMODEL];
__device__ bf16  g_att[NTOK * DMODEL];
__device__ bf16  g_mid[NTOK * 4 * DMODEL];
__device__ bf16  g_xb [NTOK * DMODEL];
__device__ bf16 g_wqkv[NLAYER * DMODEL * 3 * DMODEL];
__device__ bf16 g_wo  [NLAYER * DMODEL * DMODEL];
__device__ bf16 g_wf1 [NLAYER * DMODEL * 4 * DMODEL];
__device__ bf16 g_wf2 [NLAYER * 4 * DMODEL * DMODEL];
__device__ bf16 g_wgen[DMODEL * NVOCAB];

// ---------------------------------------------------------------------------
// helpers
// ---------------------------------------------------------------------------
__device__ __forceinline__ unsigned pk2(float a, float b)
{
    bf162 t = __floats2bfloat162_rn(a, b);
    return *(unsigned*)&t;
}

__device__ __forceinline__ void mma_tf32(float* c, unsigned a0, unsigned a1,
                                         unsigned a2, unsigned a3,
                                         unsigned b0, unsigned b1)
{
    asm volatile(
        "mma.sync.aligned.m16n8k8.row.col.f32.tf32.tf32.f32 "
        "{%0,%1,%2,%3}, {%4,%5,%6,%7}, {%8,%9}, {%0,%1,%2,%3};"
        : "+f"(c[0]), "+f"(c[1]), "+f"(c[2]), "+f"(c[3])
        : "r"(a0), "r"(a1), "r"(a2), "r"(a3), "r"(b0), "r"(b1));
}

__device__ __forceinline__ void mma_bf16(float* c, unsigned a0, unsigned a1,
                                         unsigned a2, unsigned a3,
                                         unsigned b0, unsigned b1)
{
    asm volatile(
        "mma.sync.aligned.m16n8k16.row.col.f32.bf16.bf16.f32 "
        "{%0,%1,%2,%3}, {%4,%5,%6,%7}, {%8,%9}, {%0,%1,%2,%3};"
        : "+f"(c[0]), "+f"(c[1]), "+f"(c[2]), "+f"(c[3])
        : "r"(a0), "r"(a1), "r"(a2), "r"(a3), "r"(b0), "r"(b1));
}

__device__ __forceinline__ void ldsm4(unsigned& r0, unsigned& r1,
                                      unsigned& r2, unsigned& r3, const void* p)
{
    unsigned a = (unsigned)__cvta_generic_to_shared(p);
    asm volatile("ldmatrix.sync.aligned.m8n8.x4.shared.b16 {%0,%1,%2,%3}, [%4];"
                 : "=r"(r0), "=r"(r1), "=r"(r2), "=r"(r3) : "r"(a));
}

__device__ __forceinline__ void ldsm4t(unsigned& r0, unsigned& r1,
                                       unsigned& r2, unsigned& r3, const void* p)
{
    unsigned a = (unsigned)__cvta_generic_to_shared(p);
    asm volatile("ldmatrix.sync.aligned.m8n8.x4.trans.shared.b16 {%0,%1,%2,%3}, [%4];"
                 : "=r"(r0), "=r"(r1), "=r"(r2), "=r"(r3) : "r"(a));
}

__device__ __forceinline__ void cpa16(void* smem_dst, const void* gsrc)
{
    unsigned s = (unsigned)__cvta_generic_to_shared(smem_dst);
    asm volatile("cp.async.cg.shared.global [%0], [%1], 16;\n" :: "r"(s), "l"(gsrc));
}
__device__ __forceinline__ void cpa_commit()
{
    asm volatile("cp.async.commit_group;\n" ::: "memory");
}
__device__ __forceinline__ void cpa_wait2()
{
    asm volatile("cp.async.wait_group 2;\n" ::: "memory");
}

// ---------------------------------------------------------------------------
// Fused fp32->bf16 conversion of all 5 weight tensors (one launch)
// segment sizes in float4 units:
//   qkv 98304 | wo 32768 | wf1 131072 | wf2 131072 | wgen 65536  = 458752
// ---------------------------------------------------------------------------
__global__ void cvt5_k(const float4* __restrict__ q,  const float4* __restrict__ o,
                       const float4* __restrict__ f1, const float4* __restrict__ f2,
                       const float4* __restrict__ gw,
                       uint2* __restrict__ qd,  uint2* __restrict__ od,
                       uint2* __restrict__ f1d, uint2* __restrict__ f2d,
                       uint2* __restrict__ gd)
{
    int i = blockIdx.x * 256 + threadIdx.x;
    const float4* s; uint2* d; int j = i;
    if (j < 98304)                    { s = q;  d = qd;  }
    else if ((j -= 98304)  < 32768)   { s = o;  d = od;  }
    else if ((j -= 32768)  < 131072)  { s = f1; d = f1d; }
    else if ((j -= 131072) < 131072)  { s = f2; d = f2d; }
    else { j -= 131072;                 s = gw; d = gd;  }
    float4 v = s[j];
    uint2 u;
    u.x = pk2(v.x, v.y);
    u.y = pk2(v.z, v.w);
    d[j] = u;
}

// ---------------------------------------------------------------------------
// Embedding
// ---------------------------------------------------------------------------
__global__ void embed_k(const int* __restrict__ tok, const int* __restrict__ pos,
                        const float* __restrict__ ve, const float* __restrict__ ce,
                        const float* __restrict__ pe, float* __restrict__ x)
{
    int n = blockIdx.x;
    int d = threadIdx.x;
    int p = pos[n];
    x[n * DMODEL + d] = ce[(p % 3) * DMODEL + d]
                      + pe[(p / 3) * DMODEL + d]
                      + ve[tok[n] * DMODEL + d];
}

// ---------------------------------------------------------------------------
// LayerNorm: one warp per row, fp32 in, bf16 out
// ---------------------------------------------------------------------------
__global__ void ln_k(const float* __restrict__ x, const float* __restrict__ s,
                     const float* __restrict__ b, bf16* __restrict__ y)
{
    int row  = blockIdx.x * 8 + (threadIdx.x >> 5);
    int lane = threadIdx.x & 31;
    const float4* xr = (const float4*)(x + (size_t)row * DMODEL);
    float4 v0 = xr[lane];
    float4 v1 = xr[lane + 32];

    float sum = v0.x + v0.y + v0.z + v0.w + v1.x + v1.y + v1.z + v1.w;
    #pragma unroll
    for (int o = 16; o > 0; o >>= 1) sum += __shfl_xor_sync(0xffffffffu, sum, o);
    float mu = sum * (1.0f / DMODEL);

    float d0x=v0.x-mu, d0y=v0.y-mu, d0z=v0.z-mu, d0w=v0.w-mu;
    float d1x=v1.x-mu, d1y=v1.y-mu, d1z=v1.z-mu, d1w=v1.w-mu;
    float sq = d0x*d0x+d0y*d0y+d0z*d0z+d0w*d0w + d1x*d1x+d1y*d1y+d1z*d1z+d1w*d1w;
    #pragma unroll
    for (int o = 16; o > 0; o >>= 1) sq += __shfl_xor_sync(0xffffffffu, sq, o);
    float rs = rsqrtf(sq * (1.0f / DMODEL) + 1e-5f);

    const float4* sv = (const float4*)s;
    const float4* bv = (const float4*)b;
    float4 s0 = sv[lane], s1 = sv[lane + 32];
    float4 b0 = bv[lane], b1 = bv[lane + 32];
    uint2 u0, u1;
    u0.x = pk2(d0x*rs*s0.x + b0.x, d0y*rs*s0.y + b0.y);
    u0.y = pk2(d0z*rs*s0.z + b0.z, d0w*rs*s0.w + b0.w);
    u1.x = pk2(d1x*rs*s1.x + b1.x, d1y*rs*s1.y + b1.y);
    u1.y = pk2(d1z*rs*s1.z + b1.z, d1w*rs*s1.w + b1.w);
    *(uint2*)(y + (size_t)row * DMODEL + lane * 4)        = u0;
    *(uint2*)(y + (size_t)row * DMODEL + (lane + 32) * 4) = u1;
}

// ---------------------------------------------------------------------------
// Tensor-core attention (tf32), bf16 output. One block per (batch, head).
// ---------------------------------------------------------------------------
__global__ __launch_bounds__(128)
void attn_k(const float* __restrict__ qkv, bf16* __restrict__ o)
{
    __shared__ float smb[96 * 100];
    __shared__ float zpart[4][96];
    __shared__ float zinv[96];

    int bh = blockIdx.x;
    int b = bh >> 3, h = bh & 7;
    int base = b * LSEQ;
    int tid  = threadIdx.x;
    int lane = tid & 31, wid = tid >> 5;
    int g = lane >> 2, lt = lane & 3;

    const float* Qg = qkv + (size_t)base * (3 * DMODEL) + h * DKH;
    const float* Kg = Qg + DMODEL;
    const float* Vg = Qg + 2 * DMODEL;

    unsigned vreg[12][2];
    int d0 = 8 * wid;
    #pragma unroll
    for (int kt = 0; kt < 12; kt++) {
        vreg[kt][0] = __float_as_uint(Vg[(size_t)(8 * kt + lt)     * 768 + d0 + g]);
        vreg[kt][1] = __float_as_uint(Vg[(size_t)(8 * kt + lt + 4) * 768 + d0 + g]);
    }

    for (int idx = tid; idx < 96 * 8; idx += 128) {
        int r = idx >> 3, q4 = (idx & 7) * 4;
        float4 qv = *(const float4*)(Qg + (size_t)r * 768 + q4);
        float4 kv = *(const float4*)(Kg + (size_t)r * 768 + q4);
        *(float4*)&smb[r * 36 + q4] = qv;
        *(float4*)&smb[3456 + r * 36 + q4] = kv;
    }
    __syncthreads();

    float acc[6][3][4];
    #pragma unroll
    for (int i = 0; i < 6; i++)
        #pragma unroll
        for (int j = 0; j < 3; j++)
            #pragma unroll
            for (int v = 0; v < 4; v++) acc[i][j][v] = 0.0f;

    int J0 = 3 * wid;
    #pragma unroll
    for (int kk = 0; kk < 32; kk += 8) {
        unsigned a[6][4];
        #pragma unroll
        for (int i = 0; i < 6; i++) {
            a[i][0] = __float_as_uint(smb[(16 * i + g)     * 36 + kk + lt]);
            a[i][1] = __float_as_uint(smb[(16 * i + 8 + g) * 36 + kk + lt]);
            a[i][2] = __float_as_uint(smb[(16 * i + g)     * 36 + kk + lt + 4]);
            a[i][3] = __float_as_uint(smb[(16 * i + 8 + g) * 36 + kk + lt + 4]);
        }
        #pragma unroll
        for (int jl = 0; jl < 3; jl++) {
            int J = J0 + jl;
            unsigned b0 = __float_as_uint(smb[3456 + (8 * J + g) * 36 + kk + lt]);
            unsigned b1 = __float_as_uint(smb[3456 + (8 * J + g) * 36 + kk + lt + 4]);
            #pragma unroll
            for (int i = 0; i < 6; i++)
                if (8 * J <= 16 * i + 15)
                    mma_tf32(acc[i][jl], a[i][0], a[i][1], a[i][2], a[i][3], b0, b1);
        }
    }
    __syncthreads();

    float zp[12];
    #pragma unroll
    for (int m = 0; m < 12; m++) zp[m] = 0.0f;
    const float invs = 0.17677669529663687f;

    #pragma unroll
    for (int i = 0; i < 6; i++) {
        int r0 = 16 * i + g, r1 = r0 + 8;
        #pragma unroll
        for (int jl = 0; jl < 3; jl++) {
            int J = J0 + jl;
            if (8 * J > 16 * i + 15) continue;
            int c = 8 * J + 2 * lt;
            float w0 = (c     <= r0) ? __expf(fminf(fmaxf(acc[i][jl][0] * invs, -5.0f), 5.0f)) : 0.0f;
            float w1 = (c + 1 <= r0) ? __expf(fminf(fmaxf(acc[i][jl][1] * invs, -5.0f), 5.0f)) : 0.0f;
            float w2 = (c     <= r1) ? __expf(fminf(fmaxf(acc[i][jl][2] * invs, -5.0f), 5.0f)) : 0.0f;
            float w3 = (c + 1 <= r1) ? __expf(fminf(fmaxf(acc[i][jl][3] * invs, -5.0f), 5.0f)) : 0.0f;
            zp[2 * i]     += w0 + w1;
            zp[2 * i + 1] += w2 + w3;
            float2 p0; p0.x = w0; p0.y = w1;
            float2 p1; p1.x = w2; p1.y = w3;
            *(float2*)&smb[r0 * 100 + c] = p0;
            *(float2*)&smb[r1 * 100 + c] = p1;
        }
    }
    #pragma unroll
    for (int off = 1; off <= 2; off <<= 1)
        #pragma unroll
        for (int m = 0; m < 12; m++)
            zp[m] += __shfl_xor_sync(0xffffffffu, zp[m], off);
    if (lt == 0) {
        #pragma unroll
        for (int i = 0; i < 6; i++) {
            zpart[wid][16 * i + g]     = zp[2 * i];
            zpart[wid][16 * i + 8 + g] = zp[2 * i + 1];
        }
    }
    __syncthreads();
    if (tid < 96)
        zinv[tid] = 1.0f / (zpart[0][tid] + zpart[1][tid] + zpart[2][tid] + zpart[3][tid]);
    __syncthreads();

    float oacc[6][4];
    #pragma unroll
    for (int i = 0; i < 6; i++)
        #pragma unroll
        for (int v = 0; v < 4; v++) oacc[i][v] = 0.0f;

    #pragma unroll
    for (int i = 0; i < 6; i++) {
        #pragma unroll
        for (int K2 = 0; K2 < 12; K2++) {
            if (K2 > 2 * i + 1) break;
            unsigned a0 = __float_as_uint(smb[(16 * i + g)     * 100 + 8 * K2 + lt]);
            unsigned a1 = __float_as_uint(smb[(16 * i + 8 + g) * 100 + 8 * K2 + lt]);
            unsigned a2 = __float_as_uint(smb[(16 * i + g)     * 100 + 8 * K2 + lt + 4]);
            unsigned a3 = __float_as_uint(smb[(16 * i + 8 + g) * 100 + 8 * K2 + lt + 4]);
            mma_tf32(oacc[i], a0, a1, a2, a3, vreg[K2][0], vreg[K2][1]);
        }
    }

    #pragma unroll
    for (int i = 0; i < 6; i++) {
        int r0 = 16 * i + g, r1 = r0 + 8;
        float zi0 = zinv[r0], zi1 = zinv[r1];
        unsigned u0 = pk2(oacc[i][0] * zi0, oacc[i][1] * zi0);
        unsigned u1 = pk2(oacc[i][2] * zi1, oacc[i][3] * zi1);
        *(unsigned*)(o + (size_t)(base + r0) * DMODEL + h * DKH + d0 + 2 * lt) = u0;
        *(unsigned*)(o + (size_t)(base + r1) * DMODEL + h * DKH + d0 + 2 * lt) = u1;
    }
}

// ---------------------------------------------------------------------------
// bf16 GEMM, 4-stage cp.async ring (wait_group 2), ldmatrix + mma.m16n8k16.
// BM x 128 tile, KT=16. OP: 0 bias, 1 bias+relu, 2 bias+residual.
// OUTM bit0: fp32 C; bit1: bf16 Cb.
// ---------------------------------------------------------------------------
template<int BM, int OP, int OUTM>
__global__ __launch_bounds__(256, 2)
void hgemm_k(const bf16* __restrict__ A, const bf16* __restrict__ B,
             const float* __restrict__ bias, const float* __restrict__ res,
             float* __restrict__ C, bf16* __restrict__ Cb,
             int M, int N, int K)
{
    constexpr int AST = 24;
    constexpr int BST = 136;
    __shared__ bf16 As[4][BM][AST];
    __shared__ bf16 Bs[4][16][BST];

    constexpr int MW = (BM == 128) ? 4 : 2;
    constexpr int WN = 128 / (8 / MW);
    constexpr int MI = (BM / MW) / 16;
    constexpr int NJ = WN / 8;

    int tid  = threadIdx.x;
    int lane = tid & 31, wid = tid >> 5;
    int g = lane >> 2, lt = lane & 3;
    int wm = (wid % MW) * (BM / MW);
    int wn = (wid / MW) * WN;
    int m0 = blockIdx.y * BM;
    int n0 = blockIdx.x * 128;

    int ar   = tid >> 1;
    int ah   = (tid & 1) * 8;
    int brow = tid >> 4;
    int bc8  = (tid & 15) * 8;

    int ltile = lane >> 3, lr = lane & 7;
    int a_roff = (ltile & 1) * 8 + lr;
    int a_koff = (ltile >> 1) * 8;
    int b_roff = (ltile & 1) * 8 + lr;
    int b_coff = (ltile >> 1) * 8;

    float acc[MI][NJ][4];
    #pragma unroll
    for (int i = 0; i < MI; i++)
        #pragma unroll
        for (int j = 0; j < NJ; j++)
            #pragma unroll
            for (int v = 0; v < 4; v++) acc[i][j][v] = 0.0f;

    int T = K >> 4;

    auto issue = [&](int buf, int kt) {
        int k0 = kt * 16;
        if (BM == 128 || tid < 128)
            cpa16(&As[buf][ar][ah], A + (size_t)(m0 + ar) * K + k0 + ah);
        cpa16(&Bs[buf][brow][bc8], B + (size_t)(k0 + brow) * N + n0 + bc8);
    };

    issue(0, 0); cpa_commit();
    issue(1, 1); cpa_commit();
    issue(2, 2); cpa_commit();

    for (int kt = 0; kt < T; kt++) {
        cpa_wait2();
        __syncthreads();
        if (kt + 3 < T) issue((kt + 3) & 3, kt + 3);
        cpa_commit();

        int buf = kt & 3;
        unsigned af[MI][4], bf[NJ][2];
        #pragma unroll
        for (int i = 0; i < MI; i++)
            ldsm4(af[i][0], af[i][1], af[i][2], af[i][3],
                  &As[buf][wm + 16 * i + a_roff][a_koff]);
        #pragma unroll
        for (int jp = 0; jp < NJ / 2; jp++) {
            unsigned r0, r1, r2, r3;
            ldsm4t(r0, r1, r2, r3, &Bs[buf][b_roff][wn + 16 * jp + b_coff]);
            bf[2 * jp][0] = r0;  bf[2 * jp][1] = r1;
            bf[2 * jp + 1][0] = r2;  bf[2 * jp + 1][1] = r3;
        }
        #pragma unroll
        for (int i = 0; i < MI; i++)
            #pragma unroll
            for (int j = 0; j < NJ; j++)
                mma_bf16(acc[i][j], af[i][0], af[i][1], af[i][2], af[i][3],
                         bf[j][0], bf[j][1]);
    }

    // epilogue
    #pragma unroll
    for (int i = 0; i < MI; i++) {
        int r0 = m0 + wm + 16 * i + g;
        #pragma unroll
        for (int j = 0; j < NJ; j++) {
            int c = n0 + wn + 8 * j + 2 * lt;
            float bx = bias[c], by = bias[c + 1];
            float2 v0, v1;
            v0.x = acc[i][j][0] + bx;  v0.y = acc[i][j][1] + by;
            v1.x = acc[i][j][2] + bx;  v1.y = acc[i][j][3] + by;
            if (OP == 1) {
                v0.x = fmaxf(v0.x, 0.0f); v0.y = fmaxf(v0.y, 0.0f);
                v1.x = fmaxf(v1.x, 0.0f); v1.y = fmaxf(v1.y, 0.0f);
            }
            if (OP == 2) {
                float2 r0v = *(const float2*)(res + (size_t)r0 * N + c);
                float2 r1v = *(const float2*)(res + (size_t)(r0 + 8) * N + c);
                v0.x += r0v.x; v0.y += r0v.y;
                v1.x += r1v.x; v1.y += r1v.y;
            }
            if (OUTM & 1) {
                *(float2*)(C + (size_t)r0 * N + c) = v0;
                *(float2*)(C + (size_t)(r0 + 8) * N + c) = v1;
            }
            if (OUTM & 2) {
                *(unsigned*)(Cb + (size_t)r0 * N + c) = pk2(v0.x, v0.y);
                *(unsigned*)(Cb + (size_t)(r0 + 8) * N + c) = pk2(v1.x, v1.y);
            }
        }
    }
}

// ---------------------------------------------------------------------------
// In-place log_softmax over VOCAB=1024
// ---------------------------------------------------------------------------
__global__ void lsm_k(float* __restrict__ out)
{
    __shared__ float red[256];
    int n = blockIdx.x, t = threadIdx.x;
    float v[4];
    #pragma unroll
    for (int j = 0; j < 4; j++) v[j] = out[(size_t)n * NVOCAB + t + j * 256];

    float m = fmaxf(fmaxf(v[0], v[1]), fmaxf(v[2], v[3]));
    red[t] = m;
    __syncthreads();
    #pragma unroll
    for (int o = 128; o > 0; o >>= 1) {
        if (t < o) red[t] = fmaxf(red[t], red[t + o]);
        __syncthreads();
    }
    float M = red[0];
    __syncthreads();

    float s = 0.0f;
    #pragma unroll
    for (int j = 0; j < 4; j++) s += __expf(v[j] - M);
    red[t] = s;
    __syncthreads();
    #pragma unroll
    for (int o = 128; o > 0; o >>= 1) {
        if (t < o) red[t] += red[t + o];
        __syncthreads();
    }
    float lse = M + __logf(red[0]);

    #pragma unroll
    for (int j = 0; j < 4; j++)
        out[(size_t)n * NVOCAB + t + j * 256] = v[j] - lse;
}

// ---------------------------------------------------------------------------
// Launch
// ---------------------------------------------------------------------------
extern "C" void kernel_launch(void* const* d_in, const int* in_sizes, int n_in,
                              void* d_out, int out_size)
{
    const int*   tokens    = (const int*)  d_in[0];
    const int*   pos_idx   = (const int*)  d_in[1];
    const float* value_emb = (const float*)d_in[4];
    const float* coord_emb = (const float*)d_in[5];
    const float* pos_emb   = (const float*)d_in[6];
    const float* ln1_s     = (const float*)d_in[7];
    const float* ln1_b     = (const float*)d_in[8];
    const float* W_qkv     = (const float*)d_in[9];
    const float* b_qkv     = (const float*)d_in[10];
    const float* W_o       = (const float*)d_in[11];
    const float* b_o       = (const float*)d_in[12];
    const float* ln2_s     = (const float*)d_in[13];
    const float* ln2_b     = (const float*)d_in[14];
    const float* W_ff1     = (const float*)d_in[15];
    const float* b_ff1     = (const float*)d_in[16];
    const float* W_ff2     = (const float*)d_in[17];
    const float* b_ff2     = (const float*)d_in[18];
    const float* W_gen     = (const float*)d_in[19];
    const float* b_gen     = (const float*)d_in[20];
    float* out = (float*)d_out;

    float *x, *qkv;
    bf16 *xn, *att, *mid, *xb;
    bf16 *wqkvb, *wob, *wf1b, *wf2b, *wgenb;
    cudaGetSymbolAddress((void**)&x,    g_x);
    cudaGetSymbolAddress((void**)&qkv,  g_qkv);
    cudaGetSymbolAddress((void**)&xn,   g_xn);
    cudaGetSymbolAddress((void**)&att,  g_att);
    cudaGetSymbolAddress((void**)&mid,  g_mid);
    cudaGetSymbolAddress((void**)&xb,   g_xb);
    cudaGetSymbolAddress((void**)&wqkvb, g_wqkv);
    cudaGetSymbolAddress((void**)&wob,   g_wo);
    cudaGetSymbolAddress((void**)&wf1b,  g_wf1);
    cudaGetSymbolAddress((void**)&wf2b,  g_wf2);
    cudaGetSymbolAddress((void**)&wgenb, g_wgen);

    // one fused weight-conversion launch (458752 float4s / 256 = 1792 blocks)
    cvt5_k<<<1792, 256>>>((const float4*)W_qkv, (const float4*)W_o,
                          (const float4*)W_ff1, (const float4*)W_ff2,
                          (const float4*)W_gen,
                          (uint2*)wqkvb, (uint2*)wob, (uint2*)wf1b,
                          (uint2*)wf2b, (uint2*)wgenb);

    embed_k<<<NTOK, DMODEL>>>(tokens, pos_idx, value_emb, coord_emb, pos_emb, x);

    for (int l = 0; l < NLAYER; l++) {
        const bf16* wqkv = wqkvb + (size_t)l * DMODEL * 3 * DMODEL;
        const float* bqkv = b_qkv + (size_t)l * 3 * DMODEL;
        const bf16* wo    = wob   + (size_t)l * DMODEL * DMODEL;
        const float* bo   = b_o   + (size_t)l * DMODEL;
        const bf16* wf1   = wf1b  + (size_t)l * DMODEL * 4 * DMODEL;
        const float* bf1  = b_ff1 + (size_t)l * 4 * DMODEL;
        const bf16* wf2   = wf2b  + (size_t)l * 4 * DMODEL * DMODEL;
        const float* bf2  = b_ff2 + (size_t)l * DMODEL;

        ln_k<<<NTOK / 8, 256>>>(x, ln1_s + l * DMODEL, ln1_b + l * DMODEL, xn);

        { dim3 g(3 * DMODEL / 128, NTOK / 128);
          hgemm_k<128, 0, 1><<<g, 256>>>(xn, wqkv, bqkv, nullptr, qkv, nullptr,
                                         NTOK, 3 * DMODEL, DMODEL); }

        attn_k<<<NBATCH * NHEAD, 128>>>(qkv, att);

        { dim3 g(DMODEL / 128, NTOK / 64);
          hgemm_k<64, 2, 1><<<g, 256>>>(att, wo, bo, x, x, nullptr,
                                        NTOK, DMODEL, DMODEL); }

        ln_k<<<NTOK / 8, 256>>>(x, ln2_s + l * DMODEL, ln2_b + l * DMODEL, xn);

        { dim3 g(4 * DMODEL / 128, NTOK / 128);
          hgemm_k<128, 1, 2><<<g, 256>>>(xn, wf1, bf1, nullptr, nullptr, mid,
                                         NTOK, 4 * DMODEL, DMODEL); }

        { dim3 g(DMODEL / 128, NTOK / 64);
          hgemm_k<64, 2, 3><<<g, 256>>>(mid, wf2, bf2, x, x, xb,
                                        NTOK, DMODEL, 4 * DMODEL); }
    }

    { dim3 g(NVOCAB / 128, NTOK / 128);
      hgemm_k<128, 0, 1><<<g, 256>>>(xb, wgenb, b_gen, nullptr, out, nullptr,
                                     NTOK, NVOCAB, DMODEL); }

    lsm_k<<<NTOK, 256>>>(out);
}

// round 9
// speedup vs baseline: 5.3269x; 1.0367x over previous
#include <cuda_runtime.h>
#include <cuda_bf16.h>
#include <cstdint>
#include <math.h>

#define NTOK 6144
#define DMODEL 256
#define NHEAD 8
#define DKH 32
#define NLAYER 2
#define NVOCAB 1024
#define LSEQ 96
#define NBATCH 64

typedef __nv_bfloat16 bf16;
typedef __nv_bfloat162 bf162;

// ---------------------------------------------------------------------------
// Scratch
// ---------------------------------------------------------------------------
__device__ float g_x  [NTOK * DMODEL];
__device__ bf16  g_qkvb[NTOK * 3 * DMODEL];       // bf16 qkv
__device__ bf16  g_xn [NTOK * DMODEL];
__device__ bf16  g_att[NTOK * DMODEL];
__device__ bf16  g_mid[NTOK * 4 * DMODEL];
__device__ bf16  g_xb [NTOK * DMODEL];
__device__ bf16 g_wqkv[NLAYER * DMODEL * 3 * DMODEL];
__device__ bf16 g_wo  [NLAYER * DMODEL * DMODEL];
__device__ bf16 g_wf1 [NLAYER * DMODEL * 4 * DMODEL];
__device__ bf16 g_wf2 [NLAYER * 4 * DMODEL * DMODEL];
__device__ bf16 g_wgen[DMODEL * NVOCAB];

// ---------------------------------------------------------------------------
// helpers
// ---------------------------------------------------------------------------
__device__ __forceinline__ unsigned pk2(float a, float b)
{
    bf162 t = __floats2bfloat162_rn(a, b);
    return *(unsigned*)&t;
}

__device__ __forceinline__ void mma_bf16(float* c, unsigned a0, unsigned a1,
                                         unsigned a2, unsigned a3,
                                         unsigned b0, unsigned b1)
{
    asm volatile(
        "mma.sync.aligned.m16n8k16.row.col.f32.bf16.bf16.f32 "
        "{%0,%1,%2,%3}, {%4,%5,%6,%7}, {%8,%9}, {%0,%1,%2,%3};"
        : "+f"(c[0]), "+f"(c[1]), "+f"(c[2]), "+f"(c[3])
        : "r"(a0), "r"(a1), "r"(a2), "r"(a3), "r"(b0), "r"(b1));
}

__device__ __forceinline__ void ldsm4(unsigned& r0, unsigned& r1,
                                      unsigned& r2, unsigned& r3, const void* p)
{
    unsigned a = (unsigned)__cvta_generic_to_shared(p);
    asm volatile("ldmatrix.sync.aligned.m8n8.x4.shared.b16 {%0,%1,%2,%3}, [%4];"
                 : "=r"(r0), "=r"(r1), "=r"(r2), "=r"(r3) : "r"(a));
}

__device__ __forceinline__ void ldsm4t(unsigned& r0, unsigned& r1,
                                       unsigned& r2, unsigned& r3, const void* p)
{
    unsigned a = (unsigned)__cvta_generic_to_shared(p);
    asm volatile("ldmatrix.sync.aligned.m8n8.x4.trans.shared.b16 {%0,%1,%2,%3}, [%4];"
                 : "=r"(r0), "=r"(r1), "=r"(r2), "=r"(r3) : "r"(a));
}

__device__ __forceinline__ void cpa16(void* smem_dst, const void* gsrc)
{
    unsigned s = (unsigned)__cvta_generic_to_shared(smem_dst);
    asm volatile("cp.async.cg.shared.global [%0], [%1], 16;\n" :: "r"(s), "l"(gsrc));
}
__device__ __forceinline__ void cpa_commit()
{
    asm volatile("cp.async.commit_group;\n" ::: "memory");
}
__device__ __forceinline__ void cpa_wait2()
{
    asm volatile("cp.async.wait_group 2;\n" ::: "memory");
}

// ---------------------------------------------------------------------------
// Fused fp32->bf16 conversion of all 5 weight tensors (one launch)
// ---------------------------------------------------------------------------
__global__ void cvt5_k(const float4* __restrict__ q,  const float4* __restrict__ o,
                       const float4* __restrict__ f1, const float4* __restrict__ f2,
                       const float4* __restrict__ gw,
                       uint2* __restrict__ qd,  uint2* __restrict__ od,
                       uint2* __restrict__ f1d, uint2* __restrict__ f2d,
                       uint2* __restrict__ gd)
{
    int i = blockIdx.x * 256 + threadIdx.x;
    const float4* s; uint2* d; int j = i;
    if (j < 98304)                    { s = q;  d = qd;  }
    else if ((j -= 98304)  < 32768)   { s = o;  d = od;  }
    else if ((j -= 32768)  < 131072)  { s = f1; d = f1d; }
    else if ((j -= 131072) < 131072)  { s = f2; d = f2d; }
    else { j -= 131072;                 s = gw; d = gd;  }
    float4 v = s[j];
    uint2 u;
    u.x = pk2(v.x, v.y);
    u.y = pk2(v.z, v.w);
    d[j] = u;
}

// ---------------------------------------------------------------------------
// Embedding
// ---------------------------------------------------------------------------
__global__ void embed_k(const int* __restrict__ tok, const int* __restrict__ pos,
                        const float* __restrict__ ve, const float* __restrict__ ce,
                        const float* __restrict__ pe, float* __restrict__ x)
{
    int n = blockIdx.x;
    int d = threadIdx.x;
    int p = pos[n];
    x[n * DMODEL + d] = ce[(p % 3) * DMODEL + d]
                      + pe[(p / 3) * DMODEL + d]
                      + ve[tok[n] * DMODEL + d];
}

// ---------------------------------------------------------------------------
// LayerNorm: one warp per row, fp32 in, bf16 out
// ---------------------------------------------------------------------------
__global__ void ln_k(const float* __restrict__ x, const float* __restrict__ s,
                     const float* __restrict__ b, bf16* __restrict__ y)
{
    int row  = blockIdx.x * 8 + (threadIdx.x >> 5);
    int lane = threadIdx.x & 31;
    const float4* xr = (const float4*)(x + (size_t)row * DMODEL);
    float4 v0 = xr[lane];
    float4 v1 = xr[lane + 32];

    float sum = v0.x + v0.y + v0.z + v0.w + v1.x + v1.y + v1.z + v1.w;
    #pragma unroll
    for (int o = 16; o > 0; o >>= 1) sum += __shfl_xor_sync(0xffffffffu, sum, o);
    float mu = sum * (1.0f / DMODEL);

    float d0x=v0.x-mu, d0y=v0.y-mu, d0z=v0.z-mu, d0w=v0.w-mu;
    float d1x=v1.x-mu, d1y=v1.y-mu, d1z=v1.z-mu, d1w=v1.w-mu;
    float sq = d0x*d0x+d0y*d0y+d0z*d0z+d0w*d0w + d1x*d1x+d1y*d1y+d1z*d1z+d1w*d1w;
    #pragma unroll
    for (int o = 16; o > 0; o >>= 1) sq += __shfl_xor_sync(0xffffffffu, sq, o);
    float rs = rsqrtf(sq * (1.0f / DMODEL) + 1e-5f);

    const float4* sv = (const float4*)s;
    const float4* bv = (const float4*)b;
    float4 s0 = sv[lane], s1 = sv[lane + 32];
    float4 b0 = bv[lane], b1 = bv[lane + 32];
    uint2 u0, u1;
    u0.x = pk2(d0x*rs*s0.x + b0.x, d0y*rs*s0.y + b0.y);
    u0.y = pk2(d0z*rs*s0.z + b0.z, d0w*rs*s0.w + b0.w);
    u1.x = pk2(d1x*rs*s1.x + b1.x, d1y*rs*s1.y + b1.y);
    u1.y = pk2(d1z*rs*s1.z + b1.z, d1w*rs*s1.w + b1.w);
    *(uint2*)(y + (size_t)row * DMODEL + lane * 4)        = u0;
    *(uint2*)(y + (size_t)row * DMODEL + (lane + 32) * 4) = u1;
}

// ---------------------------------------------------------------------------
// bf16 tensor-core attention. One block (128 thr) per (batch, head).
// qkv is bf16. smem chunk layout: 16-k-wide chunks of stride 24 bf16
// (proven conflict-free for ldmatrix in hgemm).
//   Q[2][96][24] @ elem 0, K[2][96][24] @ elem 4608 (phase 1)
//   P[6][96][24] @ elem 0 (phase 2, overlays Q/K after sync)
// Phase1 S=QK^T: A=Q via ldsm4; B=K (stored [n][k]) via NON-trans ldsm4,
// which lands exactly on the m16n8k16 B fragment mapping.
// Phase2 O=PV: A=P via ldsm4; B=V fragments packed from gmem.
// ---------------------------------------------------------------------------
__global__ __launch_bounds__(128)
void attn_k(const bf16* __restrict__ qkv, bf16* __restrict__ o)
{
    __shared__ bf16 sm[13824];
    __shared__ float zpart[4][96];
    __shared__ float zinv[96];

    int bh = blockIdx.x;
    int b = bh >> 3, h = bh & 7;
    int base = b * LSEQ;
    int tid  = threadIdx.x;
    int lane = tid & 31, wid = tid >> 5;
    int g = lane >> 2, lt = lane & 3;
    int ltile = lane >> 3, lr = lane & 7;
    int a_roff = (ltile & 1) * 8 + lr;
    int a_koff = (ltile >> 1) * 8;

    const bf16* Qg = qkv + (size_t)base * 768 + h * DKH;
    const bf16* Kg = Qg + DMODEL;
    const bf16* Vg = Qg + 2 * DMODEL;

    // preload V b-fragments (d-slab d0 = 8*wid), hidden behind phase 1
    unsigned vreg[6][2];
    int d0 = 8 * wid;
    #pragma unroll
    for (int kc = 0; kc < 6; kc++) {
        int k0 = 16 * kc + 2 * lt;
        unsigned lo0 = *(const unsigned short*)(Vg + (size_t)k0       * 768 + d0 + g);
        unsigned hi0 = *(const unsigned short*)(Vg + (size_t)(k0 + 1) * 768 + d0 + g);
        unsigned lo1 = *(const unsigned short*)(Vg + (size_t)(k0 + 8) * 768 + d0 + g);
        unsigned hi1 = *(const unsigned short*)(Vg + (size_t)(k0 + 9) * 768 + d0 + g);
        vreg[kc][0] = lo0 | (hi0 << 16);
        vreg[kc][1] = lo1 | (hi1 << 16);
    }

    // stage Q,K into chunked smem
    for (int idx = tid; idx < 96 * 4; idx += 128) {
        int r = idx >> 2, q = idx & 3;
        int kc = q >> 1, off8 = (q & 1) * 8;
        uint4 qv = *(const uint4*)(Qg + (size_t)r * 768 + q * 8);
        uint4 kv = *(const uint4*)(Kg + (size_t)r * 768 + q * 8);
        *(uint4*)&sm[kc * 2304 + r * 24 + off8] = qv;
        *(uint4*)&sm[4608 + kc * 2304 + r * 24 + off8] = kv;
    }
    __syncthreads();

    // ---- phase 1: S = Q K^T, warp w owns key-col slab [24w, 24w+24) ----
    float acc[6][3][4];
    #pragma unroll
    for (int i = 0; i < 6; i++)
        #pragma unroll
        for (int j = 0; j < 3; j++)
            #pragma unroll
            for (int v = 0; v < 4; v++) acc[i][j][v] = 0.0f;

    int J0 = 3 * wid;
    #pragma unroll
    for (int kc = 0; kc < 2; kc++) {
        // B fragments: tiles J0,J0+1 from first ldsm4; J0+2 (+discard) from second
        unsigned s0, s1, s2, s3, t0, t1, t2, t3;
        ldsm4(s0, s1, s2, s3,
              &sm[4608 + kc * 2304 + (24 * wid + a_roff) * 24 + a_koff]);
        ldsm4(t0, t1, t2, t3,
              &sm[4608 + kc * 2304 + (24 * wid + 16 + a_roff) * 24 + a_koff]);
        (void)t1; (void)t3;

        #pragma unroll
        for (int i = 0; i < 6; i++) {
            if (8 * J0 > 16 * i + 15) continue;   // whole row-tile masked for this warp
            unsigned a0, a1, a2, a3;
            ldsm4(a0, a1, a2, a3, &sm[kc * 2304 + (16 * i + a_roff) * 24 + a_koff]);
            if (8 * (J0 + 0) <= 16 * i + 15) mma_bf16(acc[i][0], a0, a1, a2, a3, s0, s2);
            if (8 * (J0 + 1) <= 16 * i + 15) mma_bf16(acc[i][1], a0, a1, a2, a3, s1, s3);
            if (8 * (J0 + 2) <= 16 * i + 15) mma_bf16(acc[i][2], a0, a1, a2, a3, t0, t2);
        }
    }
    __syncthreads();   // Q/K reads done; sm becomes P

    // ---- exp + causal mask -> P (bf16) + per-row z partials ----
    float zp[12];
    #pragma unroll
    for (int m = 0; m < 12; m++) zp[m] = 0.0f;
    const float invs = 0.17677669529663687f;   // 1/sqrt(32)

    #pragma unroll
    for (int i = 0; i < 6; i++) {
        int r0 = 16 * i + g, r1 = r0 + 8;
        #pragma unroll
        for (int jl = 0; jl < 3; jl++) {
            int J = J0 + jl;
            if (8 * J > 16 * i + 15) continue;
            int c = 8 * J + 2 * lt;
            float w0 = (c     <= r0) ? __expf(fminf(fmaxf(acc[i][jl][0] * invs, -5.0f), 5.0f)) : 0.0f;
            float w1 = (c + 1 <= r0) ? __expf(fminf(fmaxf(acc[i][jl][1] * invs, -5.0f), 5.0f)) : 0.0f;
            float w2 = (c     <= r1) ? __expf(fminf(fmaxf(acc[i][jl][2] * invs, -5.0f), 5.0f)) : 0.0f;
            float w3 = (c + 1 <= r1) ? __expf(fminf(fmaxf(acc[i][jl][3] * invs, -5.0f), 5.0f)) : 0.0f;
            zp[2 * i]     += w0 + w1;
            zp[2 * i + 1] += w2 + w3;
            int col = (J & 1) * 8 + 2 * lt;
            *(unsigned*)&sm[(J >> 1) * 2304 + r0 * 24 + col] = pk2(w0, w1);
            *(unsigned*)&sm[(J >> 1) * 2304 + r1 * 24 + col] = pk2(w2, w3);
        }
    }
    #pragma unroll
    for (int off = 1; off <= 2; off <<= 1)
        #pragma unroll
        for (int m = 0; m < 12; m++)
            zp[m] += __shfl_xor_sync(0xffffffffu, zp[m], off);
    if (lt == 0) {
        #pragma unroll
        for (int i = 0; i < 6; i++) {
            zpart[wid][16 * i + g]     = zp[2 * i];
            zpart[wid][16 * i + 8 + g] = zp[2 * i + 1];
        }
    }
    __syncthreads();
    if (tid < 96)
        zinv[tid] = 1.0f / (zpart[0][tid] + zpart[1][tid] + zpart[2][tid] + zpart[3][tid]);
    __syncthreads();

    // ---- phase 2: O = P V, warp w owns head-dims [8w, 8w+8) ----
    float oacc[6][4];
    #pragma unroll
    for (int i = 0; i < 6; i++)
        #pragma unroll
        for (int v = 0; v < 4; v++) oacc[i][v] = 0.0f;

    #pragma unroll
    for (int i = 0; i < 6; i++) {
        #pragma unroll
        for (int kc = 0; kc < 6; kc++) {
            if (kc > i) break;    // fully-masked k-chunks skipped
            unsigned a0, a1, a2, a3;
            ldsm4(a0, a1, a2, a3, &sm[kc * 2304 + (16 * i + a_roff) * 24 + a_koff]);
            mma_bf16(oacc[i], a0, a1, a2, a3, vreg[kc][0], vreg[kc][1]);
        }
    }

    // epilogue: divide by z, pack bf16, write
    #pragma unroll
    for (int i = 0; i < 6; i++) {
        int r0 = 16 * i + g, r1 = r0 + 8;
        float zi0 = zinv[r0], zi1 = zinv[r1];
        unsigned u0 = pk2(oacc[i][0] * zi0, oacc[i][1] * zi0);
        unsigned u1 = pk2(oacc[i][2] * zi1, oacc[i][3] * zi1);
        *(unsigned*)(o + (size_t)(base + r0) * DMODEL + h * DKH + d0 + 2 * lt) = u0;
        *(unsigned*)(o + (size_t)(base + r1) * DMODEL + h * DKH + d0 + 2 * lt) = u1;
    }
}

// ---------------------------------------------------------------------------
// bf16 GEMM, 4-stage cp.async ring (wait_group 2), ldmatrix + mma.m16n8k16.
// BM x 128 tile, KT=16. OP: 0 bias, 1 bias+relu, 2 bias+residual.
// OUTM bit0: fp32 C; bit1: bf16 Cb.
// ---------------------------------------------------------------------------
template<int BM, int OP, int OUTM>
__global__ __launch_bounds__(256, 2)
void hgemm_k(const bf16* __restrict__ A, const bf16* __restrict__ B,
             const float* __restrict__ bias, const float* __restrict__ res,
             float* __restrict__ C, bf16* __restrict__ Cb,
             int M, int N, int K)
{
    constexpr int AST = 24;
    constexpr int BST = 136;
    __shared__ bf16 As[4][BM][AST];
    __shared__ bf16 Bs[4][16][BST];

    constexpr int MW = (BM == 128) ? 4 : 2;
    constexpr int WN = 128 / (8 / MW);
    constexpr int MI = (BM / MW) / 16;
    constexpr int NJ = WN / 8;

    int tid  = threadIdx.x;
    int lane = tid & 31, wid = tid >> 5;
    int g = lane >> 2, lt = lane & 3;
    int wm = (wid % MW) * (BM / MW);
    int wn = (wid / MW) * WN;
    int m0 = blockIdx.y * BM;
    int n0 = blockIdx.x * 128;

    int ar   = tid >> 1;
    int ah   = (tid & 1) * 8;
    int brow = tid >> 4;
    int bc8  = (tid & 15) * 8;

    int ltile = lane >> 3, lr = lane & 7;
    int a_roff = (ltile & 1) * 8 + lr;
    int a_koff = (ltile >> 1) * 8;
    int b_roff = (ltile & 1) * 8 + lr;
    int b_coff = (ltile >> 1) * 8;

    float acc[MI][NJ][4];
    #pragma unroll
    for (int i = 0; i < MI; i++)
        #pragma unroll
        for (int j = 0; j < NJ; j++)
            #pragma unroll
            for (int v = 0; v < 4; v++) acc[i][j][v] = 0.0f;

    int T = K >> 4;

    auto issue = [&](int buf, int kt) {
        int k0 = kt * 16;
        if (BM == 128 || tid < 128)
            cpa16(&As[buf][ar][ah], A + (size_t)(m0 + ar) * K + k0 + ah);
        cpa16(&Bs[buf][brow][bc8], B + (size_t)(k0 + brow) * N + n0 + bc8);
    };

    issue(0, 0); cpa_commit();
    issue(1, 1); cpa_commit();
    issue(2, 2); cpa_commit();

    for (int kt = 0; kt < T; kt++) {
        cpa_wait2();
        __syncthreads();
        if (kt + 3 < T) issue((kt + 3) & 3, kt + 3);
        cpa_commit();

        int buf = kt & 3;
        unsigned af[MI][4], bf[NJ][2];
        #pragma unroll
        for (int i = 0; i < MI; i++)
            ldsm4(af[i][0], af[i][1], af[i][2], af[i][3],
                  &As[buf][wm + 16 * i + a_roff][a_koff]);
        #pragma unroll
        for (int jp = 0; jp < NJ / 2; jp++) {
            unsigned r0, r1, r2, r3;
            ldsm4t(r0, r1, r2, r3, &Bs[buf][b_roff][wn + 16 * jp + b_coff]);
            bf[2 * jp][0] = r0;  bf[2 * jp][1] = r1;
            bf[2 * jp + 1][0] = r2;  bf[2 * jp + 1][1] = r3;
        }
        #pragma unroll
        for (int i = 0; i < MI; i++)
            #pragma unroll
            for (int j = 0; j < NJ; j++)
                mma_bf16(acc[i][j], af[i][0], af[i][1], af[i][2], af[i][3],
                         bf[j][0], bf[j][1]);
    }

    // epilogue
    #pragma unroll
    for (int i = 0; i < MI; i++) {
        int r0 = m0 + wm + 16 * i + g;
        #pragma unroll
        for (int j = 0; j < NJ; j++) {
            int c = n0 + wn + 8 * j + 2 * lt;
            float bx = bias[c], by = bias[c + 1];
            float2 v0, v1;
            v0.x = acc[i][j][0] + bx;  v0.y = acc[i][j][1] + by;
            v1.x = acc[i][j][2] + bx;  v1.y = acc[i][j][3] + by;
            if (OP == 1) {
                v0.x = fmaxf(v0.x, 0.0f); v0.y = fmaxf(v0.y, 0.0f);
                v1.x = fmaxf(v1.x, 0.0f); v1.y = fmaxf(v1.y, 0.0f);
            }
            if (OP == 2) {
                float2 r0v = *(const float2*)(res + (size_t)r0 * N + c);
                float2 r1v = *(const float2*)(res + (size_t)(r0 + 8) * N + c);
                v0.x += r0v.x; v0.y += r0v.y;
                v1.x += r1v.x; v1.y += r1v.y;
            }
            if (OUTM & 1) {
                *(float2*)(C + (size_t)r0 * N + c) = v0;
                *(float2*)(C + (size_t)(r0 + 8) * N + c) = v1;
            }
            if (OUTM & 2) {
                *(unsigned*)(Cb + (size_t)r0 * N + c) = pk2(v0.x, v0.y);
                *(unsigned*)(Cb + (size_t)(r0 + 8) * N + c) = pk2(v1.x, v1.y);
            }
        }
    }
}

// ---------------------------------------------------------------------------
// In-place log_softmax over VOCAB=1024
// ---------------------------------------------------------------------------
__global__ void lsm_k(float* __restrict__ out)
{
    __shared__ float red[256];
    int n = blockIdx.x, t = threadIdx.x;
    float v[4];
    #pragma unroll
    for (int j = 0; j < 4; j++) v[j] = out[(size_t)n * NVOCAB + t + j * 256];

    float m = fmaxf(fmaxf(v[0], v[1]), fmaxf(v[2], v[3]));
    red[t] = m;
    __syncthreads();
    #pragma unroll
    for (int o = 128; o > 0; o >>= 1) {
        if (t < o) red[t] = fmaxf(red[t], red[t + o]);
        __syncthreads();
    }
    float M = red[0];
    __syncthreads();

    float s = 0.0f;
    #pragma unroll
    for (int j = 0; j < 4; j++) s += __expf(v[j] - M);
    red[t] = s;
    __syncthreads();
    #pragma unroll
    for (int o = 128; o > 0; o >>= 1) {
        if (t < o) red[t] += red[t + o];
        __syncthreads();
    }
    float lse = M + __logf(red[0]);

    #pragma unroll
    for (int j = 0; j < 4; j++)
        out[(size_t)n * NVOCAB + t + j * 256] = v[j] - lse;
}

// ---------------------------------------------------------------------------
// Launch
// ---------------------------------------------------------------------------
extern "C" void kernel_launch(void* const* d_in, const int* in_sizes, int n_in,
                              void* d_out, int out_size)
{
    const int*   tokens    = (const int*)  d_in[0];
    const int*   pos_idx   = (const int*)  d_in[1];
    const float* value_emb = (const float*)d_in[4];
    const float* coord_emb = (const float*)d_in[5];
    const float* pos_emb   = (const float*)d_in[6];
    const float* ln1_s     = (const float*)d_in[7];
    const float* ln1_b     = (const float*)d_in[8];
    const float* W_qkv     = (const float*)d_in[9];
    const float* b_qkv     = (const float*)d_in[10];
    const float* W_o       = (const float*)d_in[11];
    const float* b_o       = (const float*)d_in[12];
    const float* ln2_s     = (const float*)d_in[13];
    const float* ln2_b     = (const float*)d_in[14];
    const float* W_ff1     = (const float*)d_in[15];
    const float* b_ff1     = (const float*)d_in[16];
    const float* W_ff2     = (const float*)d_in[17];
    const float* b_ff2     = (const float*)d_in[18];
    const float* W_gen     = (const float*)d_in[19];
    const float* b_gen     = (const float*)d_in[20];
    float* out = (float*)d_out;

    float *x;
    bf16 *qkvb, *xn, *att, *mid, *xb;
    bf16 *wqkvb, *wob, *wf1b, *wf2b, *wgenb;
    cudaGetSymbolAddress((void**)&x,    g_x);
    cudaGetSymbolAddress((void**)&qkvb, g_qkvb);
    cudaGetSymbolAddress((void**)&xn,   g_xn);
    cudaGetSymbolAddress((void**)&att,  g_att);
    cudaGetSymbolAddress((void**)&mid,  g_mid);
    cudaGetSymbolAddress((void**)&xb,   g_xb);
    cudaGetSymbolAddress((void**)&wqkvb, g_wqkv);
    cudaGetSymbolAddress((void**)&wob,   g_wo);
    cudaGetSymbolAddress((void**)&wf1b,  g_wf1);
    cudaGetSymbolAddress((void**)&wf2b,  g_wf2);
    cudaGetSymbolAddress((void**)&wgenb, g_wgen);

    // one fused weight-conversion launch
    cvt5_k<<<1792, 256>>>((const float4*)W_qkv, (const float4*)W_o,
                          (const float4*)W_ff1, (const float4*)W_ff2,
                          (const float4*)W_gen,
                          (uint2*)wqkvb, (uint2*)wob, (uint2*)wf1b,
                          (uint2*)wf2b, (uint2*)wgenb);

    embed_k<<<NTOK, DMODEL>>>(tokens, pos_idx, value_emb, coord_emb, pos_emb, x);

    for (int l = 0; l < NLAYER; l++) {
        const bf16* wqkv = wqkvb + (size_t)l * DMODEL * 3 * DMODEL;
        const float* bqkv = b_qkv + (size_t)l * 3 * DMODEL;
        const bf16* wo    = wob   + (size_t)l * DMODEL * DMODEL;
        const float* bo   = b_o   + (size_t)l * DMODEL;
        const bf16* wf1   = wf1b  + (size_t)l * DMODEL * 4 * DMODEL;
        const float* bf1  = b_ff1 + (size_t)l * 4 * DMODEL;
        const bf16* wf2   = wf2b  + (size_t)l * 4 * DMODEL * DMODEL;
        const float* bf2  = b_ff2 + (size_t)l * DMODEL;

        ln_k<<<NTOK / 8, 256>>>(x, ln1_s + l * DMODEL, ln1_b + l * DMODEL, xn);

        { dim3 g(3 * DMODEL / 128, NTOK / 128);
          hgemm_k<128, 0, 2><<<g, 256>>>(xn, wqkv, bqkv, nullptr, nullptr, qkvb,
                                         NTOK, 3 * DMODEL, DMODEL); }

        attn_k<<<NBATCH * NHEAD, 128>>>(qkvb, att);

        { dim3 g(DMODEL / 128, NTOK / 64);
          hgemm_k<64, 2, 1><<<g, 256>>>(att, wo, bo, x, x, nullptr,
                                        NTOK, DMODEL, DMODEL); }

        ln_k<<<NTOK / 8, 256>>>(x, ln2_s + l * DMODEL, ln2_b + l * DMODEL, xn);

        { dim3 g(4 * DMODEL / 128, NTOK / 128);
          hgemm_k<128, 1, 2><<<g, 256>>>(xn, wf1, bf1, nullptr, nullptr, mid,
                                         NTOK, 4 * DMODEL, DMODEL); }

        { dim3 g(DMODEL / 128, NTOK / 64);
          hgemm_k<64, 2, 3><<<g, 256>>>(mid, wf2, bf2, x, x, xb,
                                        NTOK, DMODEL, 4 * DMODEL); }
    }

    { dim3 g(NVOCAB / 128, NTOK / 128);
      hgemm_k<128, 0, 1><<<g, 256>>>(xb, wgenb, b_gen, nullptr, out, nullptr,
                                     NTOK, NVOCAB, DMODEL); }

    lsm_k<<<NTOK, 256>>>(out);
}